// round 1
// baseline (speedup 1.0000x reference)
#include <cuda_runtime.h>

#define S 2048
#define HID 4096
#define NH 32
#define NKV 8
#define HD 128

// ---------------- scratch (no allocation allowed) ----------------
__device__ float g_q[(size_t)S * NH * HD];
__device__ float g_k[(size_t)S * NKV * HD];
__device__ float g_v[(size_t)S * NKV * HD];
__device__ float g_att[(size_t)S * NH * HD];

// ---------------- GEMM: C[M,N] = A[M,K] @ B[N,K]^T ----------------
#define GBM 64
#define GBN 128
#define GBK 16

__global__ __launch_bounds__(256) void gemm_abt(const float* __restrict__ A,
                                                const float* __restrict__ B,
                                                float* __restrict__ C,
                                                int M, int N, int K) {
    __shared__ float As[GBK][GBM + 4];
    __shared__ float Bs[GBK][GBN + 4];

    int tid = threadIdx.x;
    int ty = tid >> 4;      // 0..15  (4 rows each)
    int tx = tid & 15;      // 0..15  (8 cols each)
    size_t row0 = (size_t)blockIdx.y * GBM;
    size_t col0 = (size_t)blockIdx.x * GBN;

    float acc[4][8];
#pragma unroll
    for (int i = 0; i < 4; i++)
#pragma unroll
        for (int j = 0; j < 8; j++) acc[i][j] = 0.f;

    int am = tid >> 2;          // 0..63
    int ak = (tid & 3) << 2;    // 0,4,8,12
    int bm = tid >> 1;          // 0..127
    int bk = (tid & 1) << 3;    // 0 or 8

    for (int k0 = 0; k0 < K; k0 += GBK) {
        float4 a4 = *(const float4*)(A + (row0 + am) * (size_t)K + k0 + ak);
        As[ak + 0][am] = a4.x; As[ak + 1][am] = a4.y;
        As[ak + 2][am] = a4.z; As[ak + 3][am] = a4.w;

        float4 b4 = *(const float4*)(B + (col0 + bm) * (size_t)K + k0 + bk);
        Bs[bk + 0][bm] = b4.x; Bs[bk + 1][bm] = b4.y;
        Bs[bk + 2][bm] = b4.z; Bs[bk + 3][bm] = b4.w;
        float4 b5 = *(const float4*)(B + (col0 + bm) * (size_t)K + k0 + bk + 4);
        Bs[bk + 4][bm] = b5.x; Bs[bk + 5][bm] = b5.y;
        Bs[bk + 6][bm] = b5.z; Bs[bk + 7][bm] = b5.w;

        __syncthreads();

#pragma unroll
        for (int kk = 0; kk < GBK; kk++) {
            float a[4];
#pragma unroll
            for (int i = 0; i < 4; i++) a[i] = As[kk][ty * 4 + i];
            float4 b0 = *(const float4*)(&Bs[kk][tx * 8]);
            float4 b1 = *(const float4*)(&Bs[kk][tx * 8 + 4]);
            float b[8] = {b0.x, b0.y, b0.z, b0.w, b1.x, b1.y, b1.z, b1.w};
#pragma unroll
            for (int i = 0; i < 4; i++)
#pragma unroll
                for (int j = 0; j < 8; j++) acc[i][j] += a[i] * b[j];
        }
        __syncthreads();
    }

#pragma unroll
    for (int i = 0; i < 4; i++) {
        float* dst = C + (row0 + ty * 4 + i) * (size_t)N + col0 + tx * 8;
        float4 r0 = {acc[i][0], acc[i][1], acc[i][2], acc[i][3]};
        float4 r1 = {acc[i][4], acc[i][5], acc[i][6], acc[i][7]};
        *(float4*)dst = r0;
        *(float4*)(dst + 4) = r1;
    }
}

// ---------------- RoPE (in place) ----------------
__global__ void rope_kernel(float* __restrict__ x,
                            const float* __restrict__ cosp,
                            const float* __restrict__ sinp,
                            int nh, int total) {
    int idx = blockIdx.x * blockDim.x + threadIdx.x;
    if (idx >= total) return;
    int d = idx & 63;
    int h = (idx >> 6) % nh;
    int s = idx / (64 * nh);

    float c0 = cosp[s * HD + d];
    float s0 = sinp[s * HD + d];
    float c1 = cosp[s * HD + d + 64];
    float s1 = sinp[s * HD + d + 64];

    float* row = x + ((size_t)s * nh + h) * HD;
    float x0 = row[d];
    float x1 = row[d + 64];
    row[d]      = x0 * c0 - x1 * s0;
    row[d + 64] = x1 * c1 + x0 * s1;
}

// ---------------- Flash attention (fp32, causal, GQA) ----------------
#define FBQ 64
#define FBK 64
#define QSTR 132
#define PSTR 68
#define FLASH_SMEM ((3 * FBQ * QSTR + FBQ * PSTR) * 4)

__global__ __launch_bounds__(256) void flash_kernel(const float* __restrict__ Q,
                                                    const float* __restrict__ K,
                                                    const float* __restrict__ V,
                                                    float* __restrict__ O) {
    extern __shared__ float sm[];
    float* Qs = sm;
    float* Ks = Qs + FBQ * QSTR;
    float* Vs = Ks + FBQ * QSTR;
    float* Ps = Vs + FBQ * QSTR;

    int h = blockIdx.y;
    int kvh = h >> 2;   // GQA: 4 q-heads per kv-head
    int q0 = blockIdx.x * FBQ;
    int tid = threadIdx.x;
    int ty = tid >> 4;
    int tx = tid & 15;
    const float scale = 0.08838834764831845f;  // 1/sqrt(128)

    // load Q tile (scaled)
    for (int i = tid; i < FBQ * 32; i += 256) {
        int r = i >> 5;
        int d4 = (i & 31) << 2;
        float4 q = *(const float4*)(Q + ((size_t)(q0 + r) * NH + h) * HD + d4);
        q.x *= scale; q.y *= scale; q.z *= scale; q.w *= scale;
        *(float4*)(Qs + r * QSTR + d4) = q;
    }

    float m[4], l[4], o[4][8];
#pragma unroll
    for (int i = 0; i < 4; i++) {
        m[i] = -1e30f;
        l[i] = 0.f;
#pragma unroll
        for (int c = 0; c < 8; c++) o[i][c] = 0.f;
    }

    int ktmax = q0 >> 6;
    for (int kt = 0; kt <= ktmax; kt++) {
        int k0 = kt << 6;
        for (int i = tid; i < FBK * 32; i += 256) {
            int r = i >> 5;
            int d4 = (i & 31) << 2;
            *(float4*)(Ks + r * QSTR + d4) =
                *(const float4*)(K + ((size_t)(k0 + r) * NKV + kvh) * HD + d4);
            *(float4*)(Vs + r * QSTR + d4) =
                *(const float4*)(V + ((size_t)(k0 + r) * NKV + kvh) * HD + d4);
        }
        __syncthreads();

        // scores: S[64][64] = Qs @ Ks^T, 4x4 microtile
        float s4[4][4];
#pragma unroll
        for (int i = 0; i < 4; i++)
#pragma unroll
            for (int j = 0; j < 4; j++) s4[i][j] = 0.f;

        for (int d = 0; d < HD; d += 4) {
            float4 qv[4], kv[4];
#pragma unroll
            for (int i = 0; i < 4; i++)
                qv[i] = *(const float4*)(Qs + (ty * 4 + i) * QSTR + d);
#pragma unroll
            for (int j = 0; j < 4; j++)
                kv[j] = *(const float4*)(Ks + (tx * 4 + j) * QSTR + d);
#pragma unroll
            for (int i = 0; i < 4; i++)
#pragma unroll
                for (int j = 0; j < 4; j++)
                    s4[i][j] += qv[i].x * kv[j].x + qv[i].y * kv[j].y +
                                qv[i].z * kv[j].z + qv[i].w * kv[j].w;
        }

        if (kt == ktmax) {
#pragma unroll
            for (int i = 0; i < 4; i++)
#pragma unroll
                for (int j = 0; j < 4; j++)
                    if (k0 + tx * 4 + j > q0 + ty * 4 + i) s4[i][j] = -1e30f;
        }

        // online softmax per row (row r shared by 16 tx threads in a half-warp)
#pragma unroll
        for (int i = 0; i < 4; i++) {
            float rm = fmaxf(fmaxf(s4[i][0], s4[i][1]), fmaxf(s4[i][2], s4[i][3]));
            rm = fmaxf(rm, __shfl_xor_sync(0xffffffffu, rm, 1));
            rm = fmaxf(rm, __shfl_xor_sync(0xffffffffu, rm, 2));
            rm = fmaxf(rm, __shfl_xor_sync(0xffffffffu, rm, 4));
            rm = fmaxf(rm, __shfl_xor_sync(0xffffffffu, rm, 8));
            float mn = fmaxf(m[i], rm);
            float alpha = __expf(m[i] - mn);
            m[i] = mn;
            float p[4], rs = 0.f;
#pragma unroll
            for (int j = 0; j < 4; j++) {
                p[j] = __expf(s4[i][j] - mn);
                rs += p[j];
            }
            rs += __shfl_xor_sync(0xffffffffu, rs, 1);
            rs += __shfl_xor_sync(0xffffffffu, rs, 2);
            rs += __shfl_xor_sync(0xffffffffu, rs, 4);
            rs += __shfl_xor_sync(0xffffffffu, rs, 8);
            l[i] = l[i] * alpha + rs;
#pragma unroll
            for (int c = 0; c < 8; c++) o[i][c] *= alpha;
#pragma unroll
            for (int j = 0; j < 4; j++)
                Ps[(ty * 4 + i) * PSTR + tx * 4 + j] = p[j];
        }
        __syncthreads();

        // O += P @ V, 4x8 microtile
        for (int j = 0; j < FBK; j++) {
            float4 v0 = *(const float4*)(Vs + j * QSTR + tx * 8);
            float4 v1 = *(const float4*)(Vs + j * QSTR + tx * 8 + 4);
#pragma unroll
            for (int i = 0; i < 4; i++) {
                float pv = Ps[(ty * 4 + i) * PSTR + j];
                o[i][0] += pv * v0.x; o[i][1] += pv * v0.y;
                o[i][2] += pv * v0.z; o[i][3] += pv * v0.w;
                o[i][4] += pv * v1.x; o[i][5] += pv * v1.y;
                o[i][6] += pv * v1.z; o[i][7] += pv * v1.w;
            }
        }
        __syncthreads();
    }

    // epilogue
#pragma unroll
    for (int i = 0; i < 4; i++) {
        float inv = 1.0f / l[i];
        float* dst = O + ((size_t)(q0 + ty * 4 + i) * NH + h) * HD + tx * 8;
        float4 r0 = {o[i][0] * inv, o[i][1] * inv, o[i][2] * inv, o[i][3] * inv};
        float4 r1 = {o[i][4] * inv, o[i][5] * inv, o[i][6] * inv, o[i][7] * inv};
        *(float4*)dst = r0;
        *(float4*)(dst + 4) = r1;
    }
}

// ---------------- launch ----------------
extern "C" void kernel_launch(void* const* d_in, const int* in_sizes, int n_in,
                              void* d_out, int out_size) {
    const float* hs   = (const float*)d_in[0];
    // d_in[1] = attention_mask (pure causal -> applied analytically)
    const float* cosp = (const float*)d_in[2];
    const float* sinp = (const float*)d_in[3];
    const float* wq   = (const float*)d_in[4];
    const float* wk   = (const float*)d_in[5];
    const float* wv   = (const float*)d_in[6];
    const float* wo   = (const float*)d_in[7];
    float* out = (float*)d_out;

    float *qp, *kp, *vp, *ap;
    cudaGetSymbolAddress((void**)&qp, g_q);
    cudaGetSymbolAddress((void**)&kp, g_k);
    cudaGetSymbolAddress((void**)&vp, g_v);
    cudaGetSymbolAddress((void**)&ap, g_att);

    cudaFuncSetAttribute(flash_kernel,
                         cudaFuncAttributeMaxDynamicSharedMemorySize, FLASH_SMEM);

    dim3 t(256);

    // QKV projections
    gemm_abt<<<dim3((NH * HD) / GBN, S / GBM), t>>>(hs, wq, qp, S, NH * HD, HID);
    gemm_abt<<<dim3((NKV * HD) / GBN, S / GBM), t>>>(hs, wk, kp, S, NKV * HD, HID);
    gemm_abt<<<dim3((NKV * HD) / GBN, S / GBM), t>>>(hs, wv, vp, S, NKV * HD, HID);

    // RoPE
    rope_kernel<<<(S * NH * 64 + 255) / 256, 256>>>(qp, cosp, sinp, NH, S * NH * 64);
    rope_kernel<<<(S * NKV * 64 + 255) / 256, 256>>>(kp, cosp, sinp, NKV, S * NKV * 64);

    // attention
    flash_kernel<<<dim3(S / FBQ, NH), t, FLASH_SMEM>>>(qp, kp, vp, ap);

    // output projection
    gemm_abt<<<dim3(HID / GBN, S / GBM), t>>>(ap, wo, out, S, HID, HID);
}

// round 3
// speedup vs baseline: 2.4116x; 2.4116x over previous
#include <cuda_runtime.h>
#include <cstdint>

#define S 2048
#define HID 4096
#define NH 32
#define NKV 8
#define HD 128

// ---------------- scratch (no allocation allowed) ----------------
__device__ float g_q[(size_t)S * NH * HD];
__device__ float g_k[(size_t)S * NKV * HD];
__device__ float g_v[(size_t)S * NKV * HD];
__device__ float g_att[(size_t)S * NH * HD];

// ==================================================================
// tf32 mma.sync GEMM:  C[M,N] = A[M,K] @ B[N,K]^T   (all dims % tile == 0)
// CTA 128x128, BK=32, 8 warps (2 M x 4 N), warp tile 64x32,
// per warp 4x4 grid of m16n8k8 MMAs. Double-buffered smem,
// LDG.128 -> cvt.rna.tf32 -> STS.128 producer.
// ==================================================================
#define BM 128
#define BN 128
#define BK 32
#define ASTR 36                       // smem row stride in floats (conflict-free: 4r+c)
#define TILE_FLOATS (BM * ASTR)       // 4608 floats per operand tile
#define GEMM_SMEM (2 * 2 * TILE_FLOATS * 4)  // 73728 B

__device__ __forceinline__ void mma1688(float* d, const uint32_t* a, const uint32_t* b) {
    asm volatile(
        "mma.sync.aligned.m16n8k8.row.col.f32.tf32.tf32.f32 "
        "{%0,%1,%2,%3}, {%4,%5,%6,%7}, {%8,%9}, {%0,%1,%2,%3};"
        : "+f"(d[0]), "+f"(d[1]), "+f"(d[2]), "+f"(d[3])
        : "r"(a[0]), "r"(a[1]), "r"(a[2]), "r"(a[3]), "r"(b[0]), "r"(b[1]));
}

__device__ __forceinline__ uint32_t f2tf32(float x) {
    uint32_t r;
    asm("cvt.rna.tf32.f32 %0, %1;" : "=r"(r) : "f"(x));
    return r;
}

__global__ __launch_bounds__(256) void gemm_tc(const float* __restrict__ A,
                                               const float* __restrict__ B,
                                               float* __restrict__ C,
                                               int M, int N, int K) {
    extern __shared__ __align__(16) uint32_t smem[];
    uint32_t* As = smem;                       // [2][TILE_FLOATS]
    uint32_t* Bs = smem + 2 * TILE_FLOATS;     // [2][TILE_FLOATS]

    const int tid = threadIdx.x;
    const int wid = tid >> 5;
    const int lane = tid & 31;
    const int warp_m = wid & 1;        // 0..1  (64 rows each)
    const int warp_n = wid >> 1;       // 0..3  (32 cols each)
    const int lr = lane >> 2;          // 0..7
    const int lc = lane & 3;           // 0..3

    const size_t row0 = (size_t)blockIdx.y * BM;
    const size_t col0 = (size_t)blockIdx.x * BN;

    // global load mapping: 4 float4 per thread per operand tile
    const float* pa[4];
    const float* pb[4];
    uint32_t soff[4];
#pragma unroll
    for (int i = 0; i < 4; i++) {
        int f = tid + 256 * i;                 // float4 index in 128x8 grid
        int r = f >> 3, c4 = f & 7;
        pa[i] = A + (row0 + r) * (size_t)K + c4 * 4;
        pb[i] = B + (col0 + r) * (size_t)K + c4 * 4;
        soff[i] = r * ASTR + c4 * 4;
    }

    float acc[4][4][4];
#pragma unroll
    for (int mt = 0; mt < 4; mt++)
#pragma unroll
        for (int nt = 0; nt < 4; nt++)
#pragma unroll
            for (int e = 0; e < 4; e++) acc[mt][nt][e] = 0.f;

    // prefetch chunk 0
    float4 ra[4], rb[4];
#pragma unroll
    for (int i = 0; i < 4; i++) { ra[i] = *(const float4*)pa[i]; pa[i] += BK; }
#pragma unroll
    for (int i = 0; i < 4; i++) { rb[i] = *(const float4*)pb[i]; pb[i] += BK; }

    // store chunk 0 into buffer 0
#pragma unroll
    for (int i = 0; i < 4; i++) {
        uint32_t* d = As + soff[i];
        d[0] = f2tf32(ra[i].x); d[1] = f2tf32(ra[i].y);
        d[2] = f2tf32(ra[i].z); d[3] = f2tf32(ra[i].w);
        uint32_t* e = Bs + soff[i];
        e[0] = f2tf32(rb[i].x); e[1] = f2tf32(rb[i].y);
        e[2] = f2tf32(rb[i].z); e[3] = f2tf32(rb[i].w);
    }
    __syncthreads();

    const int NKc = K / BK;
    for (int kc = 0; kc < NKc; kc++) {
        const int cur = kc & 1;
        const uint32_t* Ab = As + cur * TILE_FLOATS;
        const uint32_t* Bb = Bs + cur * TILE_FLOATS;

        // prefetch next chunk into registers (latency hidden by compute)
        if (kc + 1 < NKc) {
#pragma unroll
            for (int i = 0; i < 4; i++) { ra[i] = *(const float4*)pa[i]; pa[i] += BK; }
#pragma unroll
            for (int i = 0; i < 4; i++) { rb[i] = *(const float4*)pb[i]; pb[i] += BK; }
        }

        // compute on current buffer
#pragma unroll
        for (int ks = 0; ks < 4; ks++) {
            const int k = ks * 8;
            uint32_t af[4][4], bf[4][2];
#pragma unroll
            for (int mt = 0; mt < 4; mt++) {
                const uint32_t* p = Ab + (warp_m * 64 + mt * 16 + lr) * ASTR + k + lc;
                af[mt][0] = p[0];
                af[mt][1] = p[8 * ASTR];
                af[mt][2] = p[4];
                af[mt][3] = p[8 * ASTR + 4];
            }
#pragma unroll
            for (int nt = 0; nt < 4; nt++) {
                const uint32_t* p = Bb + (warp_n * 32 + nt * 8 + lr) * ASTR + k + lc;
                bf[nt][0] = p[0];
                bf[nt][1] = p[4];
            }
#pragma unroll
            for (int mt = 0; mt < 4; mt++)
#pragma unroll
                for (int nt = 0; nt < 4; nt++)
                    mma1688(acc[mt][nt], af[mt], bf[nt]);
        }

        if (kc + 1 < NKc) {
            __syncthreads();   // all warps done reading buffer (1-cur)
            uint32_t* Aw = As + (1 - cur) * TILE_FLOATS;
            uint32_t* Bw = Bs + (1 - cur) * TILE_FLOATS;
#pragma unroll
            for (int i = 0; i < 4; i++) {
                uint32_t* d = Aw + soff[i];
                d[0] = f2tf32(ra[i].x); d[1] = f2tf32(ra[i].y);
                d[2] = f2tf32(ra[i].z); d[3] = f2tf32(ra[i].w);
                uint32_t* e = Bw + soff[i];
                e[0] = f2tf32(rb[i].x); e[1] = f2tf32(rb[i].y);
                e[2] = f2tf32(rb[i].z); e[3] = f2tf32(rb[i].w);
            }
            __syncthreads();
        }
    }

    // epilogue: c0,c1 -> (row, col..col+1), c2,c3 -> (row+8, ...)
#pragma unroll
    for (int mt = 0; mt < 4; mt++) {
        size_t rg0 = row0 + warp_m * 64 + mt * 16 + lr;
#pragma unroll
        for (int nt = 0; nt < 4; nt++) {
            size_t cg = col0 + warp_n * 32 + nt * 8 + lc * 2;
            float2 v0 = {acc[mt][nt][0], acc[mt][nt][1]};
            float2 v1 = {acc[mt][nt][2], acc[mt][nt][3]};
            *(float2*)(C + rg0 * N + cg) = v0;
            *(float2*)(C + (rg0 + 8) * N + cg) = v1;
        }
    }
}

// ---------------- RoPE (in place) ----------------
__global__ void rope_kernel(float* __restrict__ x,
                            const float* __restrict__ cosp,
                            const float* __restrict__ sinp,
                            int nh, int total) {
    int idx = blockIdx.x * blockDim.x + threadIdx.x;
    if (idx >= total) return;
    int d = idx & 63;
    int h = (idx >> 6) % nh;
    int s = idx / (64 * nh);

    float c0 = cosp[s * HD + d];
    float s0 = sinp[s * HD + d];
    float c1 = cosp[s * HD + d + 64];
    float s1 = sinp[s * HD + d + 64];

    float* row = x + ((size_t)s * nh + h) * HD;
    float x0 = row[d];
    float x1 = row[d + 64];
    row[d]      = x0 * c0 - x1 * s0;
    row[d + 64] = x1 * c1 + x0 * s1;
}

// ---------------- Flash attention (fp32, causal, GQA) ----------------
#define FBQ 64
#define FBK 64
#define QSTR 132
#define PSTR 68
#define FLASH_SMEM ((3 * FBQ * QSTR + FBQ * PSTR) * 4)

__global__ __launch_bounds__(256) void flash_kernel(const float* __restrict__ Q,
                                                    const float* __restrict__ K,
                                                    const float* __restrict__ V,
                                                    float* __restrict__ O) {
    extern __shared__ float sm[];
    float* Qs = sm;
    float* Ks = Qs + FBQ * QSTR;
    float* Vs = Ks + FBQ * QSTR;
    float* Ps = Vs + FBQ * QSTR;

    int h = blockIdx.y;
    int kvh = h >> 2;
    int q0 = blockIdx.x * FBQ;
    int tid = threadIdx.x;
    int ty = tid >> 4;
    int tx = tid & 15;
    const float scale = 0.08838834764831845f;

    for (int i = tid; i < FBQ * 32; i += 256) {
        int r = i >> 5;
        int d4 = (i & 31) << 2;
        float4 q = *(const float4*)(Q + ((size_t)(q0 + r) * NH + h) * HD + d4);
        q.x *= scale; q.y *= scale; q.z *= scale; q.w *= scale;
        *(float4*)(Qs + r * QSTR + d4) = q;
    }

    float m[4], l[4], o[4][8];
#pragma unroll
    for (int i = 0; i < 4; i++) {
        m[i] = -1e30f;
        l[i] = 0.f;
#pragma unroll
        for (int c = 0; c < 8; c++) o[i][c] = 0.f;
    }

    int ktmax = q0 >> 6;
    for (int kt = 0; kt <= ktmax; kt++) {
        int k0 = kt << 6;
        for (int i = tid; i < FBK * 32; i += 256) {
            int r = i >> 5;
            int d4 = (i & 31) << 2;
            *(float4*)(Ks + r * QSTR + d4) =
                *(const float4*)(K + ((size_t)(k0 + r) * NKV + kvh) * HD + d4);
            *(float4*)(Vs + r * QSTR + d4) =
                *(const float4*)(V + ((size_t)(k0 + r) * NKV + kvh) * HD + d4);
        }
        __syncthreads();

        float s4[4][4];
#pragma unroll
        for (int i = 0; i < 4; i++)
#pragma unroll
            for (int j = 0; j < 4; j++) s4[i][j] = 0.f;

        for (int d = 0; d < HD; d += 4) {
            float4 qv[4], kv[4];
#pragma unroll
            for (int i = 0; i < 4; i++)
                qv[i] = *(const float4*)(Qs + (ty * 4 + i) * QSTR + d);
#pragma unroll
            for (int j = 0; j < 4; j++)
                kv[j] = *(const float4*)(Ks + (tx * 4 + j) * QSTR + d);
#pragma unroll
            for (int i = 0; i < 4; i++)
#pragma unroll
                for (int j = 0; j < 4; j++)
                    s4[i][j] += qv[i].x * kv[j].x + qv[i].y * kv[j].y +
                                qv[i].z * kv[j].z + qv[i].w * kv[j].w;
        }

        if (kt == ktmax) {
#pragma unroll
            for (int i = 0; i < 4; i++)
#pragma unroll
                for (int j = 0; j < 4; j++)
                    if (k0 + tx * 4 + j > q0 + ty * 4 + i) s4[i][j] = -1e30f;
        }

#pragma unroll
        for (int i = 0; i < 4; i++) {
            float rm = fmaxf(fmaxf(s4[i][0], s4[i][1]), fmaxf(s4[i][2], s4[i][3]));
            rm = fmaxf(rm, __shfl_xor_sync(0xffffffffu, rm, 1));
            rm = fmaxf(rm, __shfl_xor_sync(0xffffffffu, rm, 2));
            rm = fmaxf(rm, __shfl_xor_sync(0xffffffffu, rm, 4));
            rm = fmaxf(rm, __shfl_xor_sync(0xffffffffu, rm, 8));
            float mn = fmaxf(m[i], rm);
            float alpha = __expf(m[i] - mn);
            m[i] = mn;
            float p[4], rs = 0.f;
#pragma unroll
            for (int j = 0; j < 4; j++) {
                p[j] = __expf(s4[i][j] - mn);
                rs += p[j];
            }
            rs += __shfl_xor_sync(0xffffffffu, rs, 1);
            rs += __shfl_xor_sync(0xffffffffu, rs, 2);
            rs += __shfl_xor_sync(0xffffffffu, rs, 4);
            rs += __shfl_xor_sync(0xffffffffu, rs, 8);
            l[i] = l[i] * alpha + rs;
#pragma unroll
            for (int c = 0; c < 8; c++) o[i][c] *= alpha;
#pragma unroll
            for (int j = 0; j < 4; j++)
                Ps[(ty * 4 + i) * PSTR + tx * 4 + j] = p[j];
        }
        __syncthreads();

        for (int j = 0; j < FBK; j++) {
            float4 v0 = *(const float4*)(Vs + j * QSTR + tx * 8);
            float4 v1 = *(const float4*)(Vs + j * QSTR + tx * 8 + 4);
#pragma unroll
            for (int i = 0; i < 4; i++) {
                float pv = Ps[(ty * 4 + i) * PSTR + j];
                o[i][0] += pv * v0.x; o[i][1] += pv * v0.y;
                o[i][2] += pv * v0.z; o[i][3] += pv * v0.w;
                o[i][4] += pv * v1.x; o[i][5] += pv * v1.y;
                o[i][6] += pv * v1.z; o[i][7] += pv * v1.w;
            }
        }
        __syncthreads();
    }

#pragma unroll
    for (int i = 0; i < 4; i++) {
        float inv = 1.0f / l[i];
        float* dst = O + ((size_t)(q0 + ty * 4 + i) * NH + h) * HD + tx * 8;
        float4 r0 = {o[i][0] * inv, o[i][1] * inv, o[i][2] * inv, o[i][3] * inv};
        float4 r1 = {o[i][4] * inv, o[i][5] * inv, o[i][6] * inv, o[i][7] * inv};
        *(float4*)dst = r0;
        *(float4*)(dst + 4) = r1;
    }
}

// ---------------- launch ----------------
extern "C" void kernel_launch(void* const* d_in, const int* in_sizes, int n_in,
                              void* d_out, int out_size) {
    const float* hs   = (const float*)d_in[0];
    const float* cosp = (const float*)d_in[2];
    const float* sinp = (const float*)d_in[3];
    const float* wq   = (const float*)d_in[4];
    const float* wk   = (const float*)d_in[5];
    const float* wv   = (const float*)d_in[6];
    const float* wo   = (const float*)d_in[7];
    float* out = (float*)d_out;

    float *qp, *kp, *vp, *ap;
    cudaGetSymbolAddress((void**)&qp, g_q);
    cudaGetSymbolAddress((void**)&kp, g_k);
    cudaGetSymbolAddress((void**)&vp, g_v);
    cudaGetSymbolAddress((void**)&ap, g_att);

    cudaFuncSetAttribute(gemm_tc,
                         cudaFuncAttributeMaxDynamicSharedMemorySize, GEMM_SMEM);
    cudaFuncSetAttribute(flash_kernel,
                         cudaFuncAttributeMaxDynamicSharedMemorySize, FLASH_SMEM);

    // QKV projections (tf32 mma.sync)
    gemm_tc<<<dim3((NH * HD) / BN, S / BM), 256, GEMM_SMEM>>>(hs, wq, qp, S, NH * HD, HID);
    gemm_tc<<<dim3((NKV * HD) / BN, S / BM), 256, GEMM_SMEM>>>(hs, wk, kp, S, NKV * HD, HID);
    gemm_tc<<<dim3((NKV * HD) / BN, S / BM), 256, GEMM_SMEM>>>(hs, wv, vp, S, NKV * HD, HID);

    // RoPE
    rope_kernel<<<(S * NH * 64 + 255) / 256, 256>>>(qp, cosp, sinp, NH, S * NH * 64);
    rope_kernel<<<(S * NKV * 64 + 255) / 256, 256>>>(kp, cosp, sinp, NKV, S * NKV * 64);

    // attention (fp32 SIMT flash — next optimization target)
    flash_kernel<<<dim3(S / FBQ, NH), 256, FLASH_SMEM>>>(qp, kp, vp, ap);

    // output projection
    gemm_tc<<<dim3(HID / BN, S / BM), 256, GEMM_SMEM>>>(ap, wo, out, S, HID, HID);
}

// round 5
// speedup vs baseline: 3.4524x; 1.4316x over previous
#include <cuda_runtime.h>
#include <cstdint>

#define S 2048
#define HID 4096
#define NH 32
#define NKV 8
#define HD 128

// ---------------- scratch (no allocation allowed) ----------------
__device__ float g_q[(size_t)S * NH * HD];
__device__ float g_k[(size_t)S * NKV * HD];
__device__ float g_v[(size_t)S * NKV * HD];
__device__ float g_att[(size_t)S * NH * HD];

// ---------------- common mma helpers ----------------
__device__ __forceinline__ void mma1688(float* d, const uint32_t* a, const uint32_t* b) {
    asm volatile(
        "mma.sync.aligned.m16n8k8.row.col.f32.tf32.tf32.f32 "
        "{%0,%1,%2,%3}, {%4,%5,%6,%7}, {%8,%9}, {%0,%1,%2,%3};"
        : "+f"(d[0]), "+f"(d[1]), "+f"(d[2]), "+f"(d[3])
        : "r"(a[0]), "r"(a[1]), "r"(a[2]), "r"(a[3]), "r"(b[0]), "r"(b[1]));
}

__device__ __forceinline__ uint32_t f2tf32(float x) {
    uint32_t r;
    asm("cvt.rna.tf32.f32 %0, %1;" : "=r"(r) : "f"(x));
    return r;
}

__device__ __forceinline__ void tf32_split(float x, uint32_t& hi, uint32_t& lo) {
    hi = f2tf32(x);
    lo = f2tf32(x - __uint_as_float(hi));
}

__device__ __forceinline__ uint32_t smem_u32(const void* p) {
    uint32_t a;
    asm("{ .reg .u64 t; cvta.to.shared.u64 t, %1; cvt.u32.u64 %0, t; }" : "=r"(a) : "l"(p));
    return a;
}

__device__ __forceinline__ void cp_async16(uint32_t saddr, const void* gaddr) {
    asm volatile("cp.async.cg.shared.global [%0], [%1], 16;"
                 :: "r"(saddr), "l"(gaddr) : "memory");
}
#define CP_COMMIT() asm volatile("cp.async.commit_group;" ::: "memory")
#define CP_WAIT1()  asm volatile("cp.async.wait_group 1;" ::: "memory")
#define CP_WAIT0()  asm volatile("cp.async.wait_group 0;" ::: "memory")

// ==================================================================
// GEMM: C[M,N] = A[M,K] @ B[N,K]^T, tf32 mma.sync.
// CTA 128x256, BK=32, 8 warps 2(M)x4(N) -> warp 64x64.
// cp.async 2-stage smem pipeline (fp32 in smem, cvt at frag load).
// ==================================================================
#define BM 128
#define BN 256
#define BK 32
#define GSTR 36
#define ASZF (BM * GSTR)                 // 4608
#define BSZF (BN * GSTR)                 // 9216
#define STGF (ASZF + BSZF)               // 13824
#define GEMM_SMEM (2 * STGF * 4)         // 110592 B

__global__ __launch_bounds__(256) void gemm_tc(const float* __restrict__ A,
                                               const float* __restrict__ B,
                                               float* __restrict__ C,
                                               int M, int N, int K) {
    extern __shared__ __align__(16) float smem[];
    const uint32_t sb = smem_u32(smem);

    const int tid = threadIdx.x;
    const int wid = tid >> 5;
    const int lane = tid & 31;
    const int wm = wid & 1;
    const int wn = wid >> 1;
    const int lr = lane >> 2;
    const int lc = lane & 3;

    const size_t row0 = (size_t)blockIdx.y * BM;
    const size_t col0 = (size_t)blockIdx.x * BN;

    const float* gA[4];
    const float* gB[8];
    uint32_t sA[4], sB[8];
#pragma unroll
    for (int i = 0; i < 4; i++) {
        int f = tid + 256 * i;
        int r = f >> 3, c4 = f & 7;
        gA[i] = A + (row0 + r) * (size_t)K + c4 * 4;
        sA[i] = (uint32_t)((r * GSTR + c4 * 4) * 4);
    }
#pragma unroll
    for (int i = 0; i < 8; i++) {
        int f = tid + 256 * i;
        int r = f >> 3, c4 = f & 7;
        gB[i] = B + (col0 + r) * (size_t)K + c4 * 4;
        sB[i] = (uint32_t)((r * GSTR + c4 * 4) * 4);
    }

    float acc[4][8][4];
#pragma unroll
    for (int mt = 0; mt < 4; mt++)
#pragma unroll
        for (int nt = 0; nt < 8; nt++)
#pragma unroll
            for (int e = 0; e < 4; e++) acc[mt][nt][e] = 0.f;

    const int NKc = K / BK;

#pragma unroll
    for (int st = 0; st < 2; st++) {
        uint32_t base = sb + st * STGF * 4;
#pragma unroll
        for (int i = 0; i < 4; i++) cp_async16(base + sA[i], gA[i] + st * BK);
#pragma unroll
        for (int i = 0; i < 8; i++) cp_async16(base + ASZF * 4 + sB[i], gB[i] + st * BK);
        CP_COMMIT();
    }

    for (int kc = 0; kc < NKc; kc++) {
        CP_WAIT1();
        __syncthreads();

        const int cur = kc & 1;
        const float* Ab = smem + cur * STGF;
        const float* Bb = smem + cur * STGF + ASZF;

#pragma unroll
        for (int ks = 0; ks < 4; ks++) {
            const int k = ks * 8;
            uint32_t af[4][4], bf[8][2];
#pragma unroll
            for (int mt = 0; mt < 4; mt++) {
                const float* p = Ab + (wm * 64 + mt * 16 + lr) * GSTR + k + lc;
                af[mt][0] = f2tf32(p[0]);
                af[mt][1] = f2tf32(p[8 * GSTR]);
                af[mt][2] = f2tf32(p[4]);
                af[mt][3] = f2tf32(p[8 * GSTR + 4]);
            }
#pragma unroll
            for (int nt = 0; nt < 8; nt++) {
                const float* p = Bb + (wn * 64 + nt * 8 + lr) * GSTR + k + lc;
                bf[nt][0] = f2tf32(p[0]);
                bf[nt][1] = f2tf32(p[4]);
            }
#pragma unroll
            for (int mt = 0; mt < 4; mt++)
#pragma unroll
                for (int nt = 0; nt < 8; nt++)
                    mma1688(acc[mt][nt], af[mt], bf[nt]);
        }
        __syncthreads();

        if (kc + 2 < NKc) {
            uint32_t base = sb + cur * STGF * 4;
            const int koff = (kc + 2) * BK;
#pragma unroll
            for (int i = 0; i < 4; i++) cp_async16(base + sA[i], gA[i] + koff);
#pragma unroll
            for (int i = 0; i < 8; i++) cp_async16(base + ASZF * 4 + sB[i], gB[i] + koff);
        }
        CP_COMMIT();
    }

#pragma unroll
    for (int mt = 0; mt < 4; mt++) {
        size_t rg = row0 + wm * 64 + mt * 16 + lr;
#pragma unroll
        for (int nt = 0; nt < 8; nt++) {
            size_t cg = col0 + wn * 64 + nt * 8 + lc * 2;
            *(float2*)(C + rg * N + cg) = make_float2(acc[mt][nt][0], acc[mt][nt][1]);
            *(float2*)(C + (rg + 8) * N + cg) = make_float2(acc[mt][nt][2], acc[mt][nt][3]);
        }
    }
}

// ---------------- RoPE (in place) ----------------
__global__ void rope_kernel(float* __restrict__ x,
                            const float* __restrict__ cosp,
                            const float* __restrict__ sinp,
                            int nh, int total) {
    int idx = blockIdx.x * blockDim.x + threadIdx.x;
    if (idx >= total) return;
    int d = idx & 63;
    int h = (idx >> 6) % nh;
    int s = idx / (64 * nh);

    float c0 = cosp[s * HD + d];
    float s0 = sinp[s * HD + d];
    float c1 = cosp[s * HD + d + 64];
    float s1 = sinp[s * HD + d + 64];

    float* row = x + ((size_t)s * nh + h) * HD;
    float x0 = row[d];
    float x1 = row[d + 64];
    row[d]      = x0 * c0 - x1 * s0;
    row[d + 64] = x1 * c1 + x0 * s1;
}

// ==================================================================
// Flash attention on tensor cores (tf32 2-term split ~= fp32)
// 128 threads (4 warps), 64 q-rows, warp owns 16 rows.
// K and V SHARE one smem buffer: load K -> QK^T -> sync ->
// issue V cp.async -> softmax (regs, overlapped) -> wait -> PV.
// SMEM = 83 KB -> 2 CTAs/SM.
// ==================================================================
#define FQ 64
#define FK 64
#define QS 132          // Q and K/V smem stride (=4 mod 32)
#define PS 68           // P smem stride, 64 cols + 4 pad (=4 mod 32)
#define FLASH_SMEM ((2 * FQ * QS + FQ * PS) * 4)   // 84992 B

__global__ __launch_bounds__(128) void flash_tc(const float* __restrict__ Q,
                                                const float* __restrict__ K,
                                                const float* __restrict__ V,
                                                float* __restrict__ O) {
    extern __shared__ __align__(16) float fsm[];
    float* Qs = fsm;                 // [64][QS]
    float* KVs = Qs + FQ * QS;       // [64][QS]  (K, then V)
    float* Ps = KVs + FQ * QS;       // [64][PS]
    const uint32_t kv_b = smem_u32(KVs);

    const int h = blockIdx.y;
    const int kvh = h >> 2;
    const int qi = gridDim.x - 1 - blockIdx.x;   // longest CTAs first
    const int q0 = qi * FQ;
    const int tid = threadIdx.x;
    const int wid = tid >> 5;
    const int lane = tid & 31;
    const int lr = lane >> 2;
    const int lc = lane & 3;
    const float scale = 0.08838834764831845f;

    // load Q tile (pre-scaled)
    for (int i = tid; i < FQ * 32; i += 128) {
        int r = i >> 5, c4 = (i & 31) << 2;
        float4 q = *(const float4*)(Q + ((size_t)(q0 + r) * NH + h) * HD + c4);
        q.x *= scale; q.y *= scale; q.z *= scale; q.w *= scale;
        *(float4*)(Qs + r * QS + c4) = q;
    }

    float o[16][4];
#pragma unroll
    for (int nt = 0; nt < 16; nt++)
#pragma unroll
        for (int e = 0; e < 4; e++) o[nt][e] = 0.f;
    float m0 = -1e30f, m1 = -1e30f, l0 = 0.f, l1 = 0.f;

    float* Pw = Ps + wid * 16 * PS;  // warp-private P band (16 rows x 64 cols)

    const int nkt = qi + 1;
    for (int kt = 0; kt < nkt; kt++) {
        const int k0 = kt * FK;

        // ---- load K tile (cp.async) ----
#pragma unroll
        for (int ii = 0; ii < 16; ii++) {
            int i = tid + 128 * ii;
            int r = i >> 5, c4 = (i & 31) << 2;
            cp_async16(kv_b + (uint32_t)((r * QS + c4) * 4),
                       K + ((size_t)(k0 + r) * NKV + kvh) * HD + c4);
        }
        CP_COMMIT();
        CP_WAIT0();
        __syncthreads();

        // ---- QK^T: 64x64, 2-term tf32 split ----
        float sa[8][4];
#pragma unroll
        for (int nt = 0; nt < 8; nt++)
#pragma unroll
            for (int e = 0; e < 4; e++) sa[nt][e] = 0.f;

#pragma unroll 4
        for (int ks = 0; ks < 16; ks++) {
            const int k = ks * 8;
            uint32_t ah[4], al[4];
            {
                const float* p = Qs + (wid * 16 + lr) * QS + k + lc;
                tf32_split(p[0], ah[0], al[0]);
                tf32_split(p[8 * QS], ah[1], al[1]);
                tf32_split(p[4], ah[2], al[2]);
                tf32_split(p[8 * QS + 4], ah[3], al[3]);
            }
#pragma unroll
            for (int nt = 0; nt < 8; nt++) {
                const float* p = KVs + (nt * 8 + lr) * QS + k + lc;
                uint32_t bh[2], bl[2];
                tf32_split(p[0], bh[0], bl[0]);
                tf32_split(p[4], bh[1], bl[1]);
                mma1688(sa[nt], ah, bh);
                mma1688(sa[nt], ah, bl);
                mma1688(sa[nt], al, bh);
            }
        }
        __syncthreads();   // all warps done reading K

        // ---- issue V load into the same buffer (overlaps softmax) ----
#pragma unroll
        for (int ii = 0; ii < 16; ii++) {
            int i = tid + 128 * ii;
            int r = i >> 5, c4 = (i & 31) << 2;
            cp_async16(kv_b + (uint32_t)((r * QS + c4) * 4),
                       V + ((size_t)(k0 + r) * NKV + kvh) * HD + c4);
        }
        CP_COMMIT();

        // ---- causal mask on diagonal tile ----
        if (kt == qi) {
            int r0 = q0 + wid * 16 + lr;
#pragma unroll
            for (int nt = 0; nt < 8; nt++) {
                int c = k0 + nt * 8 + lc * 2;
                if (c > r0)         sa[nt][0] = -1e30f;
                if (c + 1 > r0)     sa[nt][1] = -1e30f;
                if (c > r0 + 8)     sa[nt][2] = -1e30f;
                if (c + 1 > r0 + 8) sa[nt][3] = -1e30f;
            }
        }

        // ---- online softmax (rows lr and lr+8, quad reductions) ----
        float rx0 = -1e30f, rx1 = -1e30f;
#pragma unroll
        for (int nt = 0; nt < 8; nt++) {
            rx0 = fmaxf(rx0, fmaxf(sa[nt][0], sa[nt][1]));
            rx1 = fmaxf(rx1, fmaxf(sa[nt][2], sa[nt][3]));
        }
        rx0 = fmaxf(rx0, __shfl_xor_sync(0xffffffffu, rx0, 1));
        rx0 = fmaxf(rx0, __shfl_xor_sync(0xffffffffu, rx0, 2));
        rx1 = fmaxf(rx1, __shfl_xor_sync(0xffffffffu, rx1, 1));
        rx1 = fmaxf(rx1, __shfl_xor_sync(0xffffffffu, rx1, 2));

        float mn0 = fmaxf(m0, rx0), mn1 = fmaxf(m1, rx1);
        float a0 = __expf(m0 - mn0), a1 = __expf(m1 - mn1);
        m0 = mn0; m1 = mn1;

        float rs0 = 0.f, rs1 = 0.f;
#pragma unroll
        for (int nt = 0; nt < 8; nt++) {
            sa[nt][0] = __expf(sa[nt][0] - mn0);
            sa[nt][1] = __expf(sa[nt][1] - mn0);
            sa[nt][2] = __expf(sa[nt][2] - mn1);
            sa[nt][3] = __expf(sa[nt][3] - mn1);
            rs0 += sa[nt][0] + sa[nt][1];
            rs1 += sa[nt][2] + sa[nt][3];
        }
        rs0 += __shfl_xor_sync(0xffffffffu, rs0, 1);
        rs0 += __shfl_xor_sync(0xffffffffu, rs0, 2);
        rs1 += __shfl_xor_sync(0xffffffffu, rs1, 1);
        rs1 += __shfl_xor_sync(0xffffffffu, rs1, 2);
        l0 = l0 * a0 + rs0;
        l1 = l1 * a1 + rs1;

#pragma unroll
        for (int nt = 0; nt < 16; nt++) {
            o[nt][0] *= a0; o[nt][1] *= a0;
            o[nt][2] *= a1; o[nt][3] *= a1;
        }

        // write P (warp-private band)
#pragma unroll
        for (int nt = 0; nt < 8; nt++) {
            *(float2*)(Pw + lr * PS + nt * 8 + 2 * lc) = make_float2(sa[nt][0], sa[nt][1]);
            *(float2*)(Pw + (lr + 8) * PS + nt * 8 + 2 * lc) = make_float2(sa[nt][2], sa[nt][3]);
        }
        __syncwarp();

        CP_WAIT0();        // V tile landed
        __syncthreads();

        // ---- PV: O(16x128) += P(16x64) @ V(64x128), 2-term tf32 ----
#pragma unroll 2
        for (int ks = 0; ks < 8; ks++) {
            const int kk = ks * 8;
            uint32_t ah[4], al[4];
            {
                const float* p = Pw + lr * PS + kk + lc;
                tf32_split(p[0], ah[0], al[0]);
                tf32_split(p[8 * PS], ah[1], al[1]);
                tf32_split(p[4], ah[2], al[2]);
                tf32_split(p[8 * PS + 4], ah[3], al[3]);
            }
#pragma unroll
            for (int nt = 0; nt < 16; nt++) {
                const float* p = KVs + (kk + lc) * QS + nt * 8 + lr;
                uint32_t bh[2], bl[2];
                tf32_split(p[0], bh[0], bl[0]);
                tf32_split(p[4 * QS], bh[1], bl[1]);
                mma1688(o[nt], ah, bh);
                mma1688(o[nt], ah, bl);
                mma1688(o[nt], al, bh);
            }
        }
        __syncthreads();   // done reading V before next K load
    }

    // epilogue
    float inv0 = 1.0f / l0, inv1 = 1.0f / l1;
    size_t r0 = q0 + wid * 16 + lr;
#pragma unroll
    for (int nt = 0; nt < 16; nt++) {
        size_t c = nt * 8 + lc * 2;
        *(float2*)(O + (r0 * NH + h) * HD + c) =
            make_float2(o[nt][0] * inv0, o[nt][1] * inv0);
        *(float2*)(O + ((r0 + 8) * NH + h) * HD + c) =
            make_float2(o[nt][2] * inv1, o[nt][3] * inv1);
    }
}

// ---------------- launch ----------------
extern "C" void kernel_launch(void* const* d_in, const int* in_sizes, int n_in,
                              void* d_out, int out_size) {
    const float* hs   = (const float*)d_in[0];
    const float* cosp = (const float*)d_in[2];
    const float* sinp = (const float*)d_in[3];
    const float* wq   = (const float*)d_in[4];
    const float* wk   = (const float*)d_in[5];
    const float* wv   = (const float*)d_in[6];
    const float* wo   = (const float*)d_in[7];
    float* out = (float*)d_out;

    float *qp, *kp, *vp, *ap;
    cudaGetSymbolAddress((void**)&qp, g_q);
    cudaGetSymbolAddress((void**)&kp, g_k);
    cudaGetSymbolAddress((void**)&vp, g_v);
    cudaGetSymbolAddress((void**)&ap, g_att);

    cudaFuncSetAttribute(gemm_tc,
                         cudaFuncAttributeMaxDynamicSharedMemorySize, GEMM_SMEM);
    cudaFuncSetAttribute(flash_tc,
                         cudaFuncAttributeMaxDynamicSharedMemorySize, FLASH_SMEM);

    // QKV projections
    gemm_tc<<<dim3((NH * HD) / BN, S / BM), 256, GEMM_SMEM>>>(hs, wq, qp, S, NH * HD, HID);
    gemm_tc<<<dim3((NKV * HD) / BN, S / BM), 256, GEMM_SMEM>>>(hs, wk, kp, S, NKV * HD, HID);
    gemm_tc<<<dim3((NKV * HD) / BN, S / BM), 256, GEMM_SMEM>>>(hs, wv, vp, S, NKV * HD, HID);

    // RoPE
    rope_kernel<<<(S * NH * 64 + 255) / 256, 256>>>(qp, cosp, sinp, NH, S * NH * 64);
    rope_kernel<<<(S * NKV * 64 + 255) / 256, 256>>>(kp, cosp, sinp, NKV, S * NKV * 64);

    // attention (tensor-core flash)
    flash_tc<<<dim3(S / FQ, NH), 128, FLASH_SMEM>>>(qp, kp, vp, ap);

    // output projection
    gemm_tc<<<dim3(HID / BN, S / BM), 256, GEMM_SMEM>>>(ap, wo, out, S, HID, HID);
}

// round 6
// speedup vs baseline: 3.5958x; 1.0416x over previous
#include <cuda_runtime.h>
#include <cstdint>

#define S 2048
#define HID 4096
#define NH 32
#define NKV 8
#define HD 128

// ---------------- scratch (no allocation allowed) ----------------
__device__ float g_q[(size_t)S * NH * HD];
__device__ float g_k[(size_t)S * NKV * HD];
__device__ float g_v[(size_t)S * NKV * HD];
__device__ float g_att[(size_t)S * NH * HD];
// tf32-prerounded copies
__device__ float g_hs_r[(size_t)S * HID];
__device__ float g_wq_r[(size_t)NH * HD * HID];
__device__ float g_wk_r[(size_t)NKV * HD * HID];
__device__ float g_wv_r[(size_t)NKV * HD * HID];
__device__ float g_wo_r[(size_t)HID * NH * HD];

// ---------------- common helpers ----------------
__device__ __forceinline__ void mma1688(float* d, const uint32_t* a, const uint32_t* b) {
    asm volatile(
        "mma.sync.aligned.m16n8k8.row.col.f32.tf32.tf32.f32 "
        "{%0,%1,%2,%3}, {%4,%5,%6,%7}, {%8,%9}, {%0,%1,%2,%3};"
        : "+f"(d[0]), "+f"(d[1]), "+f"(d[2]), "+f"(d[3])
        : "r"(a[0]), "r"(a[1]), "r"(a[2]), "r"(a[3]), "r"(b[0]), "r"(b[1]));
}

__device__ __forceinline__ uint32_t f2tf32(float x) {
    uint32_t r;
    asm("cvt.rna.tf32.f32 %0, %1;" : "=r"(r) : "f"(x));
    return r;
}

__device__ __forceinline__ void tf32_split(float x, uint32_t& hi, uint32_t& lo) {
    hi = f2tf32(x);
    lo = f2tf32(x - __uint_as_float(hi));
}

__device__ __forceinline__ uint32_t smem_u32(const void* p) {
    uint32_t a;
    asm("{ .reg .u64 t; cvta.to.shared.u64 t, %1; cvt.u32.u64 %0, t; }" : "=r"(a) : "l"(p));
    return a;
}

__device__ __forceinline__ void cp_async16(uint32_t saddr, const void* gaddr) {
    asm volatile("cp.async.cg.shared.global [%0], [%1], 16;"
                 :: "r"(saddr), "l"(gaddr) : "memory");
}
#define CP_COMMIT() asm volatile("cp.async.commit_group;" ::: "memory")
#define CP_WAIT1()  asm volatile("cp.async.wait_group 1;" ::: "memory")
#define CP_WAIT0()  asm volatile("cp.async.wait_group 0;" ::: "memory")

// ---------------- tf32 pre-round pass ----------------
__global__ void round_tf32_kernel(const float* __restrict__ in,
                                  float* __restrict__ out, int n4) {
    int i = blockIdx.x * blockDim.x + threadIdx.x;
    if (i >= n4) return;
    float4 v = ((const float4*)in)[i];
    v.x = __uint_as_float(f2tf32(v.x));
    v.y = __uint_as_float(f2tf32(v.y));
    v.z = __uint_as_float(f2tf32(v.z));
    v.w = __uint_as_float(f2tf32(v.w));
    ((float4*)out)[i] = v;
}

// ==================================================================
// GEMM: C[M,N] = A[M,K] @ B[N,K]^T, tf32 mma.sync, inputs pre-rounded.
// CTA 128x256, BK=32, 8 warps 2(M)x4(N) -> warp 64x64.
// 3-stage cp.async pipeline, ONE __syncthreads per kc.
// ==================================================================
#define BM 128
#define BN 256
#define BK 32
#define GSTR 36
#define ASZF (BM * GSTR)                 // 4608
#define BSZF (BN * GSTR)                 // 9216
#define STGF (ASZF + BSZF)               // 13824
#define GEMM_SMEM (3 * STGF * 4)         // 165888 B

__global__ __launch_bounds__(256) void gemm_tc(const float* __restrict__ A,
                                               const float* __restrict__ B,
                                               float* __restrict__ C,
                                               int M, int N, int K) {
    extern __shared__ __align__(16) float smem[];
    const uint32_t sb = smem_u32(smem);

    const int tid = threadIdx.x;
    const int wid = tid >> 5;
    const int lane = tid & 31;
    const int wm = wid & 1;
    const int wn = wid >> 1;
    const int lr = lane >> 2;
    const int lc = lane & 3;

    const size_t row0 = (size_t)blockIdx.y * BM;
    const size_t col0 = (size_t)blockIdx.x * BN;

    const float* gA[4];
    const float* gB[8];
    uint32_t sA[4], sB[8];
#pragma unroll
    for (int i = 0; i < 4; i++) {
        int f = tid + 256 * i;
        int r = f >> 3, c4 = f & 7;
        gA[i] = A + (row0 + r) * (size_t)K + c4 * 4;
        sA[i] = (uint32_t)((r * GSTR + c4 * 4) * 4);
    }
#pragma unroll
    for (int i = 0; i < 8; i++) {
        int f = tid + 256 * i;
        int r = f >> 3, c4 = f & 7;
        gB[i] = B + (col0 + r) * (size_t)K + c4 * 4;
        sB[i] = (uint32_t)((r * GSTR + c4 * 4) * 4);
    }

    float acc[4][8][4];
#pragma unroll
    for (int mt = 0; mt < 4; mt++)
#pragma unroll
        for (int nt = 0; nt < 8; nt++)
#pragma unroll
            for (int e = 0; e < 4; e++) acc[mt][nt][e] = 0.f;

    const int NKc = K / BK;

    // prologue: stages 0,1
#pragma unroll
    for (int st = 0; st < 2; st++) {
        uint32_t base = sb + st * STGF * 4;
#pragma unroll
        for (int i = 0; i < 4; i++) cp_async16(base + sA[i], gA[i] + st * BK);
#pragma unroll
        for (int i = 0; i < 8; i++) cp_async16(base + ASZF * 4 + sB[i], gB[i] + st * BK);
        CP_COMMIT();
    }

    int ld_slot = 2;     // stage index (mod 3) for next load
    int cp_slot = 0;     // stage index (mod 3) to compute
    for (int kc = 0; kc < NKc; kc++) {
        CP_WAIT1();          // stage kc landed (<=1 group pending)
        __syncthreads();     // all warps done with compute kc-1 AND see stage kc

        // issue load for stage kc+2 into slot freed by compute kc-1
        if (kc + 2 < NKc) {
            uint32_t base = sb + ld_slot * STGF * 4;
            const int koff = (kc + 2) * BK;
#pragma unroll
            for (int i = 0; i < 4; i++) cp_async16(base + sA[i], gA[i] + koff);
#pragma unroll
            for (int i = 0; i < 8; i++) cp_async16(base + ASZF * 4 + sB[i], gB[i] + koff);
        }
        CP_COMMIT();         // always commit (possibly empty group)
        ld_slot = (ld_slot == 2) ? 0 : ld_slot + 1;

        const uint32_t* Ab = (const uint32_t*)(smem + cp_slot * STGF);
        const uint32_t* Bb = (const uint32_t*)(smem + cp_slot * STGF + ASZF);
        cp_slot = (cp_slot == 2) ? 0 : cp_slot + 1;

#pragma unroll
        for (int ks = 0; ks < 4; ks++) {
            const int k = ks * 8;
            uint32_t af[4][4], bf[8][2];
#pragma unroll
            for (int mt = 0; mt < 4; mt++) {
                const uint32_t* p = Ab + (wm * 64 + mt * 16 + lr) * GSTR + k + lc;
                af[mt][0] = p[0];
                af[mt][1] = p[8 * GSTR];
                af[mt][2] = p[4];
                af[mt][3] = p[8 * GSTR + 4];
            }
#pragma unroll
            for (int nt = 0; nt < 8; nt++) {
                const uint32_t* p = Bb + (wn * 64 + nt * 8 + lr) * GSTR + k + lc;
                bf[nt][0] = p[0];
                bf[nt][1] = p[4];
            }
#pragma unroll
            for (int mt = 0; mt < 4; mt++)
#pragma unroll
                for (int nt = 0; nt < 8; nt++)
                    mma1688(acc[mt][nt], af[mt], bf[nt]);
        }
    }

#pragma unroll
    for (int mt = 0; mt < 4; mt++) {
        size_t rg = row0 + wm * 64 + mt * 16 + lr;
#pragma unroll
        for (int nt = 0; nt < 8; nt++) {
            size_t cg = col0 + wn * 64 + nt * 8 + lc * 2;
            *(float2*)(C + rg * N + cg) = make_float2(acc[mt][nt][0], acc[mt][nt][1]);
            *(float2*)(C + (rg + 8) * N + cg) = make_float2(acc[mt][nt][2], acc[mt][nt][3]);
        }
    }
}

// ---------------- RoPE (in place) ----------------
__global__ void rope_kernel(float* __restrict__ x,
                            const float* __restrict__ cosp,
                            const float* __restrict__ sinp,
                            int nh, int total) {
    int idx = blockIdx.x * blockDim.x + threadIdx.x;
    if (idx >= total) return;
    int d = idx & 63;
    int h = (idx >> 6) % nh;
    int s = idx / (64 * nh);

    float c0 = cosp[s * HD + d];
    float s0 = sinp[s * HD + d];
    float c1 = cosp[s * HD + d + 64];
    float s1 = sinp[s * HD + d + 64];

    float* row = x + ((size_t)s * nh + h) * HD;
    float x0 = row[d];
    float x1 = row[d + 64];
    row[d]      = x0 * c0 - x1 * s0;
    row[d + 64] = x1 * c1 + x0 * s1;
}

// ==================================================================
// Flash attention on tensor cores (tf32 2-term split ~= fp32)
// 128 threads (4 warps), 64 q-rows, warp owns 16 rows.
// K/V share one buffer; stride 136 (=8 mod 32) -> all frag loads
// conflict-free. Epilogue emits tf32-rounded att for out-proj.
// ==================================================================
#define FQ 64
#define FK 64
#define QS 136          // Q and K/V smem stride (=8 mod 32)
#define PS 68           // P smem stride (=4 mod 32)
#define FLASH_SMEM ((2 * FQ * QS + FQ * PS) * 4)   // 87040 B

__global__ __launch_bounds__(128) void flash_tc(const float* __restrict__ Q,
                                                const float* __restrict__ K,
                                                const float* __restrict__ V,
                                                float* __restrict__ O) {
    extern __shared__ __align__(16) float fsm[];
    float* Qs = fsm;                 // [64][QS]
    float* KVs = Qs + FQ * QS;       // [64][QS]  (K, then V)
    float* Ps = KVs + FQ * QS;       // [64][PS]
    const uint32_t kv_b = smem_u32(KVs);

    const int h = blockIdx.y;
    const int kvh = h >> 2;
    const int qi = gridDim.x - 1 - blockIdx.x;   // longest CTAs first
    const int q0 = qi * FQ;
    const int tid = threadIdx.x;
    const int wid = tid >> 5;
    const int lane = tid & 31;
    const int lr = lane >> 2;
    const int lc = lane & 3;
    const float scale = 0.08838834764831845f;

    for (int i = tid; i < FQ * 32; i += 128) {
        int r = i >> 5, c4 = (i & 31) << 2;
        float4 q = *(const float4*)(Q + ((size_t)(q0 + r) * NH + h) * HD + c4);
        q.x *= scale; q.y *= scale; q.z *= scale; q.w *= scale;
        *(float4*)(Qs + r * QS + c4) = q;
    }

    float o[16][4];
#pragma unroll
    for (int nt = 0; nt < 16; nt++)
#pragma unroll
        for (int e = 0; e < 4; e++) o[nt][e] = 0.f;
    float m0 = -1e30f, m1 = -1e30f, l0 = 0.f, l1 = 0.f;

    float* Pw = Ps + wid * 16 * PS;

    const int nkt = qi + 1;
    for (int kt = 0; kt < nkt; kt++) {
        const int k0 = kt * FK;

#pragma unroll
        for (int ii = 0; ii < 16; ii++) {
            int i = tid + 128 * ii;
            int r = i >> 5, c4 = (i & 31) << 2;
            cp_async16(kv_b + (uint32_t)((r * QS + c4) * 4),
                       K + ((size_t)(k0 + r) * NKV + kvh) * HD + c4);
        }
        CP_COMMIT();
        CP_WAIT0();
        __syncthreads();

        // ---- QK^T ----
        float sa[8][4];
#pragma unroll
        for (int nt = 0; nt < 8; nt++)
#pragma unroll
            for (int e = 0; e < 4; e++) sa[nt][e] = 0.f;

#pragma unroll 4
        for (int ks = 0; ks < 16; ks++) {
            const int k = ks * 8;
            uint32_t ah[4], al[4];
            {
                const float* p = Qs + (wid * 16 + lr) * QS + k + lc;
                tf32_split(p[0], ah[0], al[0]);
                tf32_split(p[8 * QS], ah[1], al[1]);
                tf32_split(p[4], ah[2], al[2]);
                tf32_split(p[8 * QS + 4], ah[3], al[3]);
            }
#pragma unroll
            for (int nt = 0; nt < 8; nt++) {
                const float* p = KVs + (nt * 8 + lr) * QS + k + lc;
                uint32_t bh[2], bl[2];
                tf32_split(p[0], bh[0], bl[0]);
                tf32_split(p[4], bh[1], bl[1]);
                mma1688(sa[nt], ah, bh);
                mma1688(sa[nt], ah, bl);
                mma1688(sa[nt], al, bh);
            }
        }
        __syncthreads();   // done reading K

        // ---- V load into same buffer (overlaps softmax) ----
#pragma unroll
        for (int ii = 0; ii < 16; ii++) {
            int i = tid + 128 * ii;
            int r = i >> 5, c4 = (i & 31) << 2;
            cp_async16(kv_b + (uint32_t)((r * QS + c4) * 4),
                       V + ((size_t)(k0 + r) * NKV + kvh) * HD + c4);
        }
        CP_COMMIT();

        if (kt == qi) {
            int r0 = q0 + wid * 16 + lr;
#pragma unroll
            for (int nt = 0; nt < 8; nt++) {
                int c = k0 + nt * 8 + lc * 2;
                if (c > r0)         sa[nt][0] = -1e30f;
                if (c + 1 > r0)     sa[nt][1] = -1e30f;
                if (c > r0 + 8)     sa[nt][2] = -1e30f;
                if (c + 1 > r0 + 8) sa[nt][3] = -1e30f;
            }
        }

        float rx0 = -1e30f, rx1 = -1e30f;
#pragma unroll
        for (int nt = 0; nt < 8; nt++) {
            rx0 = fmaxf(rx0, fmaxf(sa[nt][0], sa[nt][1]));
            rx1 = fmaxf(rx1, fmaxf(sa[nt][2], sa[nt][3]));
        }
        rx0 = fmaxf(rx0, __shfl_xor_sync(0xffffffffu, rx0, 1));
        rx0 = fmaxf(rx0, __shfl_xor_sync(0xffffffffu, rx0, 2));
        rx1 = fmaxf(rx1, __shfl_xor_sync(0xffffffffu, rx1, 1));
        rx1 = fmaxf(rx1, __shfl_xor_sync(0xffffffffu, rx1, 2));

        float mn0 = fmaxf(m0, rx0), mn1 = fmaxf(m1, rx1);
        float a0 = __expf(m0 - mn0), a1 = __expf(m1 - mn1);
        m0 = mn0; m1 = mn1;

        float rs0 = 0.f, rs1 = 0.f;
#pragma unroll
        for (int nt = 0; nt < 8; nt++) {
            sa[nt][0] = __expf(sa[nt][0] - mn0);
            sa[nt][1] = __expf(sa[nt][1] - mn0);
            sa[nt][2] = __expf(sa[nt][2] - mn1);
            sa[nt][3] = __expf(sa[nt][3] - mn1);
            rs0 += sa[nt][0] + sa[nt][1];
            rs1 += sa[nt][2] + sa[nt][3];
        }
        rs0 += __shfl_xor_sync(0xffffffffu, rs0, 1);
        rs0 += __shfl_xor_sync(0xffffffffu, rs0, 2);
        rs1 += __shfl_xor_sync(0xffffffffu, rs1, 1);
        rs1 += __shfl_xor_sync(0xffffffffu, rs1, 2);
        l0 = l0 * a0 + rs0;
        l1 = l1 * a1 + rs1;

#pragma unroll
        for (int nt = 0; nt < 16; nt++) {
            o[nt][0] *= a0; o[nt][1] *= a0;
            o[nt][2] *= a1; o[nt][3] *= a1;
        }

#pragma unroll
        for (int nt = 0; nt < 8; nt++) {
            *(float2*)(Pw + lr * PS + nt * 8 + 2 * lc) = make_float2(sa[nt][0], sa[nt][1]);
            *(float2*)(Pw + (lr + 8) * PS + nt * 8 + 2 * lc) = make_float2(sa[nt][2], sa[nt][3]);
        }
        __syncwarp();

        CP_WAIT0();        // V landed
        __syncthreads();

        // ---- PV ----
#pragma unroll 2
        for (int ks = 0; ks < 8; ks++) {
            const int kk = ks * 8;
            uint32_t ah[4], al[4];
            {
                const float* p = Pw + lr * PS + kk + lc;
                tf32_split(p[0], ah[0], al[0]);
                tf32_split(p[8 * PS], ah[1], al[1]);
                tf32_split(p[4], ah[2], al[2]);
                tf32_split(p[8 * PS + 4], ah[3], al[3]);
            }
#pragma unroll
            for (int nt = 0; nt < 16; nt++) {
                const float* p = KVs + (kk + lc) * QS + nt * 8 + lr;
                uint32_t bh[2], bl[2];
                tf32_split(p[0], bh[0], bl[0]);
                tf32_split(p[4 * QS], bh[1], bl[1]);
                mma1688(o[nt], ah, bh);
                mma1688(o[nt], ah, bl);
                mma1688(o[nt], al, bh);
            }
        }
        __syncthreads();
    }

    // epilogue — emit tf32-rounded att (out-proj A operand)
    float inv0 = 1.0f / l0, inv1 = 1.0f / l1;
    size_t r0 = q0 + wid * 16 + lr;
#pragma unroll
    for (int nt = 0; nt < 16; nt++) {
        size_t c = nt * 8 + lc * 2;
        float2 v0 = make_float2(__uint_as_float(f2tf32(o[nt][0] * inv0)),
                                __uint_as_float(f2tf32(o[nt][1] * inv0)));
        float2 v1 = make_float2(__uint_as_float(f2tf32(o[nt][2] * inv1)),
                                __uint_as_float(f2tf32(o[nt][3] * inv1)));
        *(float2*)(O + (r0 * NH + h) * HD + c) = v0;
        *(float2*)(O + ((r0 + 8) * NH + h) * HD + c) = v1;
    }
}

// ---------------- launch ----------------
extern "C" void kernel_launch(void* const* d_in, const int* in_sizes, int n_in,
                              void* d_out, int out_size) {
    const float* hs   = (const float*)d_in[0];
    const float* cosp = (const float*)d_in[2];
    const float* sinp = (const float*)d_in[3];
    const float* wq   = (const float*)d_in[4];
    const float* wk   = (const float*)d_in[5];
    const float* wv   = (const float*)d_in[6];
    const float* wo   = (const float*)d_in[7];
    float* out = (float*)d_out;

    float *qp, *kp, *vp, *ap, *hsr, *wqr, *wkr, *wvr, *wor;
    cudaGetSymbolAddress((void**)&qp, g_q);
    cudaGetSymbolAddress((void**)&kp, g_k);
    cudaGetSymbolAddress((void**)&vp, g_v);
    cudaGetSymbolAddress((void**)&ap, g_att);
    cudaGetSymbolAddress((void**)&hsr, g_hs_r);
    cudaGetSymbolAddress((void**)&wqr, g_wq_r);
    cudaGetSymbolAddress((void**)&wkr, g_wk_r);
    cudaGetSymbolAddress((void**)&wvr, g_wv_r);
    cudaGetSymbolAddress((void**)&wor, g_wo_r);

    cudaFuncSetAttribute(gemm_tc,
                         cudaFuncAttributeMaxDynamicSharedMemorySize, GEMM_SMEM);
    cudaFuncSetAttribute(flash_tc,
                         cudaFuncAttributeMaxDynamicSharedMemorySize, FLASH_SMEM);

    const int RT = 256;
    int n_hs = S * HID / 4, n_wq = NH * HD * HID / 4, n_wk = NKV * HD * HID / 4;

    // (0..2) pre-round hs, wq, wk
    round_tf32_kernel<<<n_hs / RT, RT>>>(hs, hsr, n_hs);
    round_tf32_kernel<<<n_wq / RT, RT>>>(wq, wqr, n_wq);
    round_tf32_kernel<<<n_wk / RT, RT>>>(wk, wkr, n_wk);
    // (3) Q projection — lands in the ncu capture slot
    gemm_tc<<<dim3((NH * HD) / BN, S / BM), 256, GEMM_SMEM>>>(hsr, wqr, qp, S, NH * HD, HID);
    // (4,5) remaining pre-rounds
    round_tf32_kernel<<<n_wk / RT, RT>>>(wv, wvr, n_wk);
    round_tf32_kernel<<<n_wq / RT, RT>>>(wo, wor, n_wq);
    // (6,7) K/V projections
    gemm_tc<<<dim3((NKV * HD) / BN, S / BM), 256, GEMM_SMEM>>>(hsr, wkr, kp, S, NKV * HD, HID);
    gemm_tc<<<dim3((NKV * HD) / BN, S / BM), 256, GEMM_SMEM>>>(hsr, wvr, vp, S, NKV * HD, HID);
    // (8,9) RoPE
    rope_kernel<<<(S * NH * 64 + 255) / 256, 256>>>(qp, cosp, sinp, NH, S * NH * 64);
    rope_kernel<<<(S * NKV * 64 + 255) / 256, 256>>>(kp, cosp, sinp, NKV, S * NKV * 64);
    // (10) attention
    flash_tc<<<dim3(S / FQ, NH), 128, FLASH_SMEM>>>(qp, kp, vp, ap);
    // (11) output projection
    gemm_tc<<<dim3(HID / BN, S / BM), 256, GEMM_SMEM>>>(ap, wor, out, S, HID, HID);
}

// round 7
// speedup vs baseline: 4.0822x; 1.1353x over previous
#include <cuda_runtime.h>
#include <cstdint>

#define S 2048
#define HID 4096
#define NH 32
#define NKV 8
#define HD 128
#define QKVN 6144            // 4096 (q) + 1024 (k) + 1024 (v)

// ---------------- scratch (no allocation allowed) ----------------
__device__ float g_qkv[(size_t)S * QKVN];
__device__ float g_att[(size_t)S * NH * HD];
__device__ float g_hs_r[(size_t)S * HID];
__device__ float g_wq_r[(size_t)NH * HD * HID];
__device__ float g_wk_r[(size_t)NKV * HD * HID];
__device__ float g_wv_r[(size_t)NKV * HD * HID];
__device__ float g_wo_r[(size_t)HID * NH * HD];

// ---------------- common helpers ----------------
__device__ __forceinline__ void mma1688(float* d, const uint32_t* a, const uint32_t* b) {
    asm volatile(
        "mma.sync.aligned.m16n8k8.row.col.f32.tf32.tf32.f32 "
        "{%0,%1,%2,%3}, {%4,%5,%6,%7}, {%8,%9}, {%0,%1,%2,%3};"
        : "+f"(d[0]), "+f"(d[1]), "+f"(d[2]), "+f"(d[3])
        : "r"(a[0]), "r"(a[1]), "r"(a[2]), "r"(a[3]), "r"(b[0]), "r"(b[1]));
}

__device__ __forceinline__ uint32_t f2tf32(float x) {
    uint32_t r;
    asm("cvt.rna.tf32.f32 %0, %1;" : "=r"(r) : "f"(x));
    return r;
}

__device__ __forceinline__ void tf32_split(float x, uint32_t& hi, uint32_t& lo) {
    hi = f2tf32(x);
    lo = f2tf32(x - __uint_as_float(hi));
}

__device__ __forceinline__ uint32_t smem_u32(const void* p) {
    uint32_t a;
    asm("{ .reg .u64 t; cvta.to.shared.u64 t, %1; cvt.u32.u64 %0, t; }" : "=r"(a) : "l"(p));
    return a;
}

__device__ __forceinline__ void cp_async16(uint32_t saddr, const void* gaddr) {
    asm volatile("cp.async.cg.shared.global [%0], [%1], 16;"
                 :: "r"(saddr), "l"(gaddr) : "memory");
}
#define CP_COMMIT() asm volatile("cp.async.commit_group;" ::: "memory")
#define CP_WAIT1()  asm volatile("cp.async.wait_group 1;" ::: "memory")
#define CP_WAIT0()  asm volatile("cp.async.wait_group 0;" ::: "memory")

// ---------------- tf32 pre-round passes ----------------
__global__ void round_tf32_kernel(const float* __restrict__ in,
                                  float* __restrict__ out, int n4) {
    int i = blockIdx.x * blockDim.x + threadIdx.x;
    if (i >= n4) return;
    float4 v = ((const float4*)in)[i];
    v.x = __uint_as_float(f2tf32(v.x));
    v.y = __uint_as_float(f2tf32(v.y));
    v.z = __uint_as_float(f2tf32(v.z));
    v.w = __uint_as_float(f2tf32(v.w));
    ((float4*)out)[i] = v;
}

__global__ void round2_tf32_kernel(const float* __restrict__ inA, float* __restrict__ outA, int n4A,
                                   const float* __restrict__ inB, float* __restrict__ outB, int n4B) {
    int i = blockIdx.x * blockDim.x + threadIdx.x;
    const float4* src;
    float4* dst;
    int j;
    if (i < n4A) { src = (const float4*)inA; dst = (float4*)outA; j = i; }
    else { j = i - n4A; if (j >= n4B) return; src = (const float4*)inB; dst = (float4*)outB; }
    float4 v = src[j];
    v.x = __uint_as_float(f2tf32(v.x));
    v.y = __uint_as_float(f2tf32(v.y));
    v.z = __uint_as_float(f2tf32(v.z));
    v.w = __uint_as_float(f2tf32(v.w));
    dst[j] = v;
}

// ==================================================================
// GEMM: C[M,N] = A[M,K] @ B[N,K]^T (B split across <=3 weight mats).
// CTA 128x128, BK=32, 8 warps 2(M)x4(N) -> warp 64x32.
// 3-stage cp.async pipeline, 2 CTAs/SM (launch_bounds(256,2)).
// ==================================================================
#define BM 128
#define BN 128
#define BK 32
#define GSTR 36
#define TSZF (BM * GSTR)                 // 4608 floats per operand tile
#define STGF (2 * TSZF)                  // 9216
#define GEMM_SMEM (3 * STGF * 4)         // 110592 B

__global__ __launch_bounds__(256, 2) void gemm_tc(
        const float* __restrict__ A,
        const float* __restrict__ B0, const float* __restrict__ B1,
        const float* __restrict__ B2, int nb0, int nb1,
        float* __restrict__ C, int M, int N, int K) {
    extern __shared__ __align__(16) float smem[];
    const uint32_t sb = smem_u32(smem);

    const int tid = threadIdx.x;
    const int wid = tid >> 5;
    const int lane = tid & 31;
    const int wm = wid & 1;            // 64 rows
    const int wn = wid >> 1;           // 32 cols
    const int lr = lane >> 2;
    const int lc = lane & 3;

    const size_t row0 = (size_t)blockIdx.y * BM;
    const int col0 = blockIdx.x * BN;

    // select weight slice for this column block
    const float* B;
    int bo;
    if (col0 < nb0)      { B = B0; bo = col0; }
    else if (col0 < nb1) { B = B1; bo = col0 - nb0; }
    else                 { B = B2; bo = col0 - nb1; }

    // producer: thread covers rows r0+32i, fixed c4
    const int r0 = tid >> 3;
    const int c4 = (tid & 7) << 2;
    const float* gA = A + (row0 + r0) * (size_t)K + c4;
    const float* gB = B + (size_t)(bo + r0) * K + c4;
    const uint32_t sOffA = (uint32_t)((r0 * GSTR + c4) * 4);
    const size_t gstep = (size_t)32 * K;

    float acc[4][4][4];
#pragma unroll
    for (int mt = 0; mt < 4; mt++)
#pragma unroll
        for (int nt = 0; nt < 4; nt++)
#pragma unroll
            for (int e = 0; e < 4; e++) acc[mt][nt][e] = 0.f;

    const int NKc = K / BK;

#pragma unroll
    for (int st = 0; st < 2; st++) {
        uint32_t base = sb + st * STGF * 4;
#pragma unroll
        for (int i = 0; i < 4; i++) {
            cp_async16(base + sOffA + i * (32 * GSTR * 4), gA + i * gstep + st * BK);
            cp_async16(base + TSZF * 4 + sOffA + i * (32 * GSTR * 4), gB + i * gstep + st * BK);
        }
        CP_COMMIT();
    }

    int ld_slot = 2, cp_slot = 0;
    for (int kc = 0; kc < NKc; kc++) {
        CP_WAIT1();
        __syncthreads();

        if (kc + 2 < NKc) {
            uint32_t base = sb + ld_slot * STGF * 4;
            const int koff = (kc + 2) * BK;
#pragma unroll
            for (int i = 0; i < 4; i++) {
                cp_async16(base + sOffA + i * (32 * GSTR * 4), gA + i * gstep + koff);
                cp_async16(base + TSZF * 4 + sOffA + i * (32 * GSTR * 4), gB + i * gstep + koff);
            }
        }
        CP_COMMIT();
        ld_slot = (ld_slot == 2) ? 0 : ld_slot + 1;

        const uint32_t* Ab = (const uint32_t*)(smem + cp_slot * STGF);
        const uint32_t* Bb = (const uint32_t*)(smem + cp_slot * STGF + TSZF);
        cp_slot = (cp_slot == 2) ? 0 : cp_slot + 1;

#pragma unroll
        for (int ks = 0; ks < 4; ks++) {
            const int k = ks * 8;
            uint32_t af[4][4], bf[4][2];
#pragma unroll
            for (int mt = 0; mt < 4; mt++) {
                const uint32_t* p = Ab + (wm * 64 + mt * 16 + lr) * GSTR + k + lc;
                af[mt][0] = p[0];
                af[mt][1] = p[8 * GSTR];
                af[mt][2] = p[4];
                af[mt][3] = p[8 * GSTR + 4];
            }
#pragma unroll
            for (int nt = 0; nt < 4; nt++) {
                const uint32_t* p = Bb + (wn * 32 + nt * 8 + lr) * GSTR + k + lc;
                bf[nt][0] = p[0];
                bf[nt][1] = p[4];
            }
#pragma unroll
            for (int mt = 0; mt < 4; mt++)
#pragma unroll
                for (int nt = 0; nt < 4; nt++)
                    mma1688(acc[mt][nt], af[mt], bf[nt]);
        }
    }

#pragma unroll
    for (int mt = 0; mt < 4; mt++) {
        size_t rg = row0 + wm * 64 + mt * 16 + lr;
#pragma unroll
        for (int nt = 0; nt < 4; nt++) {
            size_t cg = (size_t)col0 + wn * 32 + nt * 8 + lc * 2;
            *(float2*)(C + rg * N + cg) = make_float2(acc[mt][nt][0], acc[mt][nt][1]);
            *(float2*)(C + (rg + 8) * N + cg) = make_float2(acc[mt][nt][2], acc[mt][nt][3]);
        }
    }
}

// ---------------- RoPE (in place, fused-qkv layout) ----------------
__global__ void rope_kernel(float* __restrict__ x,
                            const float* __restrict__ cosp,
                            const float* __restrict__ sinp,
                            int nh, int total) {
    int idx = blockIdx.x * blockDim.x + threadIdx.x;
    if (idx >= total) return;
    int d = idx & 63;
    int h = (idx >> 6) % nh;
    int s = idx / (64 * nh);

    float c0 = cosp[s * HD + d];
    float s0 = sinp[s * HD + d];
    float c1 = cosp[s * HD + d + 64];
    float s1 = sinp[s * HD + d + 64];

    float* row = x + (size_t)s * QKVN + h * HD;
    float x0 = row[d];
    float x1 = row[d + 64];
    row[d]      = x0 * c0 - x1 * s0;
    row[d + 64] = x1 * c1 + x0 * s1;
}

// ==================================================================
// Flash attention on tensor cores (tf32 2-term split ~= fp32)
// Reads fused qkv layout (row stride QKVN).
// ==================================================================
#define FQ 64
#define FK 64
#define QS 136
#define PS 68
#define FLASH_SMEM ((2 * FQ * QS + FQ * PS) * 4)   // 87040 B

__global__ __launch_bounds__(128) void flash_tc(const float* __restrict__ QKV,
                                                float* __restrict__ O) {
    extern __shared__ __align__(16) float fsm[];
    float* Qs = fsm;
    float* KVs = Qs + FQ * QS;
    float* Ps = KVs + FQ * QS;
    const uint32_t kv_b = smem_u32(KVs);

    const int h = blockIdx.y;
    const int kvh = h >> 2;
    const int qi = gridDim.x - 1 - blockIdx.x;
    const int q0 = qi * FQ;
    const int tid = threadIdx.x;
    const int wid = tid >> 5;
    const int lane = tid & 31;
    const int lr = lane >> 2;
    const int lc = lane & 3;
    const float scale = 0.08838834764831845f;

    const float* Qg = QKV + h * HD;                    // q block
    const float* Kg = QKV + 4096 + kvh * HD;           // k block
    const float* Vg = QKV + 5120 + kvh * HD;           // v block

    for (int i = tid; i < FQ * 32; i += 128) {
        int r = i >> 5, c4 = (i & 31) << 2;
        float4 q = *(const float4*)(Qg + (size_t)(q0 + r) * QKVN + c4);
        q.x *= scale; q.y *= scale; q.z *= scale; q.w *= scale;
        *(float4*)(Qs + r * QS + c4) = q;
    }

    float o[16][4];
#pragma unroll
    for (int nt = 0; nt < 16; nt++)
#pragma unroll
        for (int e = 0; e < 4; e++) o[nt][e] = 0.f;
    float m0 = -1e30f, m1 = -1e30f, l0 = 0.f, l1 = 0.f;

    float* Pw = Ps + wid * 16 * PS;

    const int nkt = qi + 1;
    for (int kt = 0; kt < nkt; kt++) {
        const int k0 = kt * FK;

#pragma unroll
        for (int ii = 0; ii < 16; ii++) {
            int i = tid + 128 * ii;
            int r = i >> 5, c4 = (i & 31) << 2;
            cp_async16(kv_b + (uint32_t)((r * QS + c4) * 4),
                       Kg + (size_t)(k0 + r) * QKVN + c4);
        }
        CP_COMMIT();
        CP_WAIT0();
        __syncthreads();

        float sa[8][4];
#pragma unroll
        for (int nt = 0; nt < 8; nt++)
#pragma unroll
            for (int e = 0; e < 4; e++) sa[nt][e] = 0.f;

#pragma unroll 4
        for (int ks = 0; ks < 16; ks++) {
            const int k = ks * 8;
            uint32_t ah[4], al[4];
            {
                const float* p = Qs + (wid * 16 + lr) * QS + k + lc;
                tf32_split(p[0], ah[0], al[0]);
                tf32_split(p[8 * QS], ah[1], al[1]);
                tf32_split(p[4], ah[2], al[2]);
                tf32_split(p[8 * QS + 4], ah[3], al[3]);
            }
#pragma unroll
            for (int nt = 0; nt < 8; nt++) {
                const float* p = KVs + (nt * 8 + lr) * QS + k + lc;
                uint32_t bh[2], bl[2];
                tf32_split(p[0], bh[0], bl[0]);
                tf32_split(p[4], bh[1], bl[1]);
                mma1688(sa[nt], ah, bh);
                mma1688(sa[nt], ah, bl);
                mma1688(sa[nt], al, bh);
            }
        }
        __syncthreads();

#pragma unroll
        for (int ii = 0; ii < 16; ii++) {
            int i = tid + 128 * ii;
            int r = i >> 5, c4 = (i & 31) << 2;
            cp_async16(kv_b + (uint32_t)((r * QS + c4) * 4),
                       Vg + (size_t)(k0 + r) * QKVN + c4);
        }
        CP_COMMIT();

        if (kt == qi) {
            int r0 = q0 + wid * 16 + lr;
#pragma unroll
            for (int nt = 0; nt < 8; nt++) {
                int c = k0 + nt * 8 + lc * 2;
                if (c > r0)         sa[nt][0] = -1e30f;
                if (c + 1 > r0)     sa[nt][1] = -1e30f;
                if (c > r0 + 8)     sa[nt][2] = -1e30f;
                if (c + 1 > r0 + 8) sa[nt][3] = -1e30f;
            }
        }

        float rx0 = -1e30f, rx1 = -1e30f;
#pragma unroll
        for (int nt = 0; nt < 8; nt++) {
            rx0 = fmaxf(rx0, fmaxf(sa[nt][0], sa[nt][1]));
            rx1 = fmaxf(rx1, fmaxf(sa[nt][2], sa[nt][3]));
        }
        rx0 = fmaxf(rx0, __shfl_xor_sync(0xffffffffu, rx0, 1));
        rx0 = fmaxf(rx0, __shfl_xor_sync(0xffffffffu, rx0, 2));
        rx1 = fmaxf(rx1, __shfl_xor_sync(0xffffffffu, rx1, 1));
        rx1 = fmaxf(rx1, __shfl_xor_sync(0xffffffffu, rx1, 2));

        float mn0 = fmaxf(m0, rx0), mn1 = fmaxf(m1, rx1);
        float a0 = __expf(m0 - mn0), a1 = __expf(m1 - mn1);
        m0 = mn0; m1 = mn1;

        float rs0 = 0.f, rs1 = 0.f;
#pragma unroll
        for (int nt = 0; nt < 8; nt++) {
            sa[nt][0] = __expf(sa[nt][0] - mn0);
            sa[nt][1] = __expf(sa[nt][1] - mn0);
            sa[nt][2] = __expf(sa[nt][2] - mn1);
            sa[nt][3] = __expf(sa[nt][3] - mn1);
            rs0 += sa[nt][0] + sa[nt][1];
            rs1 += sa[nt][2] + sa[nt][3];
        }
        rs0 += __shfl_xor_sync(0xffffffffu, rs0, 1);
        rs0 += __shfl_xor_sync(0xffffffffu, rs0, 2);
        rs1 += __shfl_xor_sync(0xffffffffu, rs1, 1);
        rs1 += __shfl_xor_sync(0xffffffffu, rs1, 2);
        l0 = l0 * a0 + rs0;
        l1 = l1 * a1 + rs1;

#pragma unroll
        for (int nt = 0; nt < 16; nt++) {
            o[nt][0] *= a0; o[nt][1] *= a0;
            o[nt][2] *= a1; o[nt][3] *= a1;
        }

#pragma unroll
        for (int nt = 0; nt < 8; nt++) {
            *(float2*)(Pw + lr * PS + nt * 8 + 2 * lc) = make_float2(sa[nt][0], sa[nt][1]);
            *(float2*)(Pw + (lr + 8) * PS + nt * 8 + 2 * lc) = make_float2(sa[nt][2], sa[nt][3]);
        }
        __syncwarp();

        CP_WAIT0();
        __syncthreads();

#pragma unroll 2
        for (int ks = 0; ks < 8; ks++) {
            const int kk = ks * 8;
            uint32_t ah[4], al[4];
            {
                const float* p = Pw + lr * PS + kk + lc;
                tf32_split(p[0], ah[0], al[0]);
                tf32_split(p[8 * PS], ah[1], al[1]);
                tf32_split(p[4], ah[2], al[2]);
                tf32_split(p[8 * PS + 4], ah[3], al[3]);
            }
#pragma unroll
            for (int nt = 0; nt < 16; nt++) {
                const float* p = KVs + (kk + lc) * QS + nt * 8 + lr;
                uint32_t bh[2], bl[2];
                tf32_split(p[0], bh[0], bl[0]);
                tf32_split(p[4 * QS], bh[1], bl[1]);
                mma1688(o[nt], ah, bh);
                mma1688(o[nt], ah, bl);
                mma1688(o[nt], al, bh);
            }
        }
        __syncthreads();
    }

    float inv0 = 1.0f / l0, inv1 = 1.0f / l1;
    size_t r0 = q0 + wid * 16 + lr;
#pragma unroll
    for (int nt = 0; nt < 16; nt++) {
        size_t c = nt * 8 + lc * 2;
        float2 v0 = make_float2(__uint_as_float(f2tf32(o[nt][0] * inv0)),
                                __uint_as_float(f2tf32(o[nt][1] * inv0)));
        float2 v1 = make_float2(__uint_as_float(f2tf32(o[nt][2] * inv1)),
                                __uint_as_float(f2tf32(o[nt][3] * inv1)));
        *(float2*)(O + (r0 * NH + h) * HD + c) = v0;
        *(float2*)(O + ((r0 + 8) * NH + h) * HD + c) = v1;
    }
}

// ---------------- launch ----------------
extern "C" void kernel_launch(void* const* d_in, const int* in_sizes, int n_in,
                              void* d_out, int out_size) {
    const float* hs   = (const float*)d_in[0];
    const float* cosp = (const float*)d_in[2];
    const float* sinp = (const float*)d_in[3];
    const float* wq   = (const float*)d_in[4];
    const float* wk   = (const float*)d_in[5];
    const float* wv   = (const float*)d_in[6];
    const float* wo   = (const float*)d_in[7];
    float* out = (float*)d_out;

    float *qkv, *ap, *hsr, *wqr, *wkr, *wvr, *wor;
    cudaGetSymbolAddress((void**)&qkv, g_qkv);
    cudaGetSymbolAddress((void**)&ap, g_att);
    cudaGetSymbolAddress((void**)&hsr, g_hs_r);
    cudaGetSymbolAddress((void**)&wqr, g_wq_r);
    cudaGetSymbolAddress((void**)&wkr, g_wk_r);
    cudaGetSymbolAddress((void**)&wvr, g_wv_r);
    cudaGetSymbolAddress((void**)&wor, g_wo_r);

    cudaFuncSetAttribute(gemm_tc,
                         cudaFuncAttributeMaxDynamicSharedMemorySize, GEMM_SMEM);
    cudaFuncSetAttribute(flash_tc,
                         cudaFuncAttributeMaxDynamicSharedMemorySize, FLASH_SMEM);

    const int RT = 256;
    const int n_hs = S * HID / 4;
    const int n_wq = NH * HD * HID / 4;
    const int n_wk = NKV * HD * HID / 4;

    // (0) round hs  (1) round wq  (2) round wk+wv (one launch)
    round_tf32_kernel<<<n_hs / RT, RT>>>(hs, hsr, n_hs);
    round_tf32_kernel<<<n_wq / RT, RT>>>(wq, wqr, n_wq);
    round2_tf32_kernel<<<(2 * n_wk + RT - 1) / RT, RT>>>(wk, wkr, n_wk, wv, wvr, n_wk);
    // (3) fused QKV projection — ncu capture slot
    gemm_tc<<<dim3(QKVN / BN, S / BM), 256, GEMM_SMEM>>>(
        hsr, wqr, wkr, wvr, NH * HD, NH * HD + NKV * HD, qkv, S, QKVN, HID);
    // (4) round wo
    round_tf32_kernel<<<n_wq / RT, RT>>>(wo, wor, n_wq);
    // (5,6) RoPE on q and k slices of fused buffer
    rope_kernel<<<(S * NH * 64 + 255) / 256, 256>>>(qkv, cosp, sinp, NH, S * NH * 64);
    rope_kernel<<<(S * NKV * 64 + 255) / 256, 256>>>(qkv + 4096, cosp, sinp, NKV, S * NKV * 64);
    // (7) attention
    flash_tc<<<dim3(S / FQ, NH), 128, FLASH_SMEM>>>(qkv, ap);
    // (8) output projection
    gemm_tc<<<dim3(HID / BN, S / BM), 256, GEMM_SMEM>>>(
        ap, wor, wor, wor, HID, HID, out, S, HID, HID);
}

// round 8
// speedup vs baseline: 6.0290x; 1.4769x over previous
#include <cuda_runtime.h>
#include <cuda_fp16.h>
#include <cstdint>

#define S 2048
#define HID 4096
#define NH 32
#define NKV 8
#define HD 128
#define QKVN 6144            // 4096 (q) + 1024 (k) + 1024 (v)

// ---------------- scratch (no allocation allowed) ----------------
__device__ float  g_qkv[(size_t)S * QKVN];
__device__ __half g_att_h[(size_t)S * NH * HD];
__device__ __half g_hs_h[(size_t)S * HID];
__device__ __half g_wq_h[(size_t)NH * HD * HID];
__device__ __half g_wk_h[(size_t)NKV * HD * HID];
__device__ __half g_wv_h[(size_t)NKV * HD * HID];
__device__ __half g_wo_h[(size_t)HID * NH * HD];

// ---------------- helpers ----------------
__device__ __forceinline__ void mma16816(float* d, uint32_t a0, uint32_t a1,
                                         uint32_t a2, uint32_t a3,
                                         uint32_t b0, uint32_t b1) {
    asm volatile(
        "mma.sync.aligned.m16n8k16.row.col.f32.f16.f16.f32 "
        "{%0,%1,%2,%3}, {%4,%5,%6,%7}, {%8,%9}, {%0,%1,%2,%3};"
        : "+f"(d[0]), "+f"(d[1]), "+f"(d[2]), "+f"(d[3])
        : "r"(a0), "r"(a1), "r"(a2), "r"(a3), "r"(b0), "r"(b1));
}

__device__ __forceinline__ void mma1688(float* d, const uint32_t* a, const uint32_t* b) {
    asm volatile(
        "mma.sync.aligned.m16n8k8.row.col.f32.tf32.tf32.f32 "
        "{%0,%1,%2,%3}, {%4,%5,%6,%7}, {%8,%9}, {%0,%1,%2,%3};"
        : "+f"(d[0]), "+f"(d[1]), "+f"(d[2]), "+f"(d[3])
        : "r"(a[0]), "r"(a[1]), "r"(a[2]), "r"(a[3]), "r"(b[0]), "r"(b[1]));
}

__device__ __forceinline__ uint32_t f2tf32(float x) {
    uint32_t r;
    asm("cvt.rna.tf32.f32 %0, %1;" : "=r"(r) : "f"(x));
    return r;
}

__device__ __forceinline__ void tf32_split(float x, uint32_t& hi, uint32_t& lo) {
    hi = f2tf32(x);
    lo = f2tf32(x - __uint_as_float(hi));
}

__device__ __forceinline__ uint32_t smem_u32(const void* p) {
    uint32_t a;
    asm("{ .reg .u64 t; cvta.to.shared.u64 t, %1; cvt.u32.u64 %0, t; }" : "=r"(a) : "l"(p));
    return a;
}

__device__ __forceinline__ void cp_async16(uint32_t saddr, const void* gaddr) {
    asm volatile("cp.async.cg.shared.global [%0], [%1], 16;"
                 :: "r"(saddr), "l"(gaddr) : "memory");
}
#define CP_COMMIT() asm volatile("cp.async.commit_group;" ::: "memory")
#define CP_WAIT1()  asm volatile("cp.async.wait_group 1;" ::: "memory")
#define CP_WAIT0()  asm volatile("cp.async.wait_group 0;" ::: "memory")

__device__ __forceinline__ void lds64(uint32_t& x, uint32_t& y, uint32_t addr) {
    asm volatile("ld.shared.v2.b32 {%0,%1}, [%2];" : "=r"(x), "=r"(y) : "r"(addr));
}

// ---------------- fp16 pre-round with k16-group interleave ----------------
// group of 16 halves stored as pairs: (0,1),(8,9),(2,3),(10,11),(4,5),(12,13),(6,7),(14,15)
__device__ __forceinline__ void round_group(const float* src, __half* dst) {
    float s[16];
#pragma unroll
    for (int i = 0; i < 4; i++) {
        float4 v = ((const float4*)src)[i];
        s[4 * i] = v.x; s[4 * i + 1] = v.y; s[4 * i + 2] = v.z; s[4 * i + 3] = v.w;
    }
    __half2 w[8];
#pragma unroll
    for (int lc = 0; lc < 4; lc++) {
        __half2 a; a.x = __float2half_rn(s[2 * lc]);     a.y = __float2half_rn(s[2 * lc + 1]);
        __half2 b; b.x = __float2half_rn(s[8 + 2 * lc]); b.y = __float2half_rn(s[8 + 2 * lc + 1]);
        w[2 * lc] = a; w[2 * lc + 1] = b;
    }
    uint4* d4 = (uint4*)dst;
    d4[0] = *(uint4*)&w[0];
    d4[1] = *(uint4*)&w[4];
}

__global__ void round_fp16_kernel(const float* __restrict__ in,
                                  __half* __restrict__ out, int ng) {
    int g = blockIdx.x * blockDim.x + threadIdx.x;
    if (g >= ng) return;
    round_group(in + (size_t)g * 16, out + (size_t)g * 16);
}

__global__ void round2_fp16_kernel(const float* __restrict__ inA, __half* __restrict__ outA, int ngA,
                                   const float* __restrict__ inB, __half* __restrict__ outB, int ngB) {
    int g = blockIdx.x * blockDim.x + threadIdx.x;
    if (g < ngA) { round_group(inA + (size_t)g * 16, outA + (size_t)g * 16); return; }
    g -= ngA;
    if (g < ngB) round_group(inB + (size_t)g * 16, outB + (size_t)g * 16);
}

// ==================================================================
// fp16 GEMM: C[M,N] = A[M,K] @ B[N,K]^T  (A,B half, k16-interleaved)
// CTA 128x128, BK=64, 8 warps 2(M)x4(N) -> warp 64x32.
// 2-stage cp.async, 2 CTAs/SM.
// Row in smem: 64 halves (128B data) padded to 160B (40 words, ≡8 mod 32).
// ==================================================================
#define BM 128
#define BN 128
#define BK 64
#define ROWB 160                          // bytes per smem row
#define TILEB (BM * ROWB)                 // 20480 B per operand tile
#define STAGEB (2 * TILEB)                // 40960 B
#define GEMM_SMEM (2 * STAGEB)            // 81920 B

__global__ __launch_bounds__(256, 2) void gemm_tc(
        const __half* __restrict__ A,
        const __half* __restrict__ B0, const __half* __restrict__ B1,
        const __half* __restrict__ B2, int nb0, int nb1,
        float* __restrict__ C, int M, int N, int K) {
    extern __shared__ __align__(16) char smem[];
    const uint32_t sb = smem_u32(smem);

    const int tid = threadIdx.x;
    const int wid = tid >> 5;
    const int lane = tid & 31;
    const int wm = wid & 1;            // 64 rows
    const int wn = wid >> 1;           // 32 cols
    const int lr = lane >> 2;
    const int lc = lane & 3;

    const size_t row0 = (size_t)blockIdx.y * BM;
    const int col0 = blockIdx.x * BN;

    const __half* B;
    int bo;
    if (col0 < nb0)      { B = B0; bo = col0; }
    else if (col0 < nb1) { B = B1; bo = col0 - nb0; }
    else                 { B = B2; bo = col0 - nb1; }

    // producer: 4 chunks A + 4 chunks B per thread (chunk = 16B = 8 halves)
    const int cr = tid >> 1;                   // base row pair: chunks tid, tid+256...
    // chunk id layout: cid = tid + 256*i ; r = cid/8, c = cid%8
    const __half* gA[4];
    const __half* gB[4];
    uint32_t sOff[4];
#pragma unroll
    for (int i = 0; i < 4; i++) {
        int cid = tid + 256 * i;
        int r = cid >> 3, c = cid & 7;
        gA[i] = A + (row0 + r) * (size_t)K + c * 8;
        gB[i] = B + (size_t)(bo + r) * K + c * 8;
        sOff[i] = (uint32_t)(r * ROWB + c * 16);
    }
    (void)cr;

    float acc[4][4][4];
#pragma unroll
    for (int mt = 0; mt < 4; mt++)
#pragma unroll
        for (int nt = 0; nt < 4; nt++)
#pragma unroll
            for (int e = 0; e < 4; e++) acc[mt][nt][e] = 0.f;

    const int NKc = K / BK;

    // prologue: stages 0,1
#pragma unroll
    for (int st = 0; st < 2; st++) {
        uint32_t base = sb + st * STAGEB;
#pragma unroll
        for (int i = 0; i < 4; i++) {
            cp_async16(base + sOff[i], gA[i] + st * BK);
            cp_async16(base + TILEB + sOff[i], gB[i] + st * BK);
        }
        CP_COMMIT();
    }

    for (int kc = 0; kc < NKc; kc++) {
        CP_WAIT1();
        __syncthreads();

        const uint32_t Abase = sb + (kc & 1) * STAGEB;
        const uint32_t Bbase = Abase + TILEB;

#pragma unroll
        for (int g = 0; g < 4; g++) {
            const uint32_t go = (uint32_t)(g * 32 + lc * 8);
            uint32_t af[4][4], bf[4][2];
#pragma unroll
            for (int mt = 0; mt < 4; mt++) {
                uint32_t r = (uint32_t)((wm * 64 + mt * 16 + lr) * ROWB) + go;
                lds64(af[mt][0], af[mt][2], Abase + r);
                lds64(af[mt][1], af[mt][3], Abase + r + 8 * ROWB);
            }
#pragma unroll
            for (int nt = 0; nt < 4; nt++) {
                uint32_t r = (uint32_t)((wn * 32 + nt * 8 + lr) * ROWB) + go;
                lds64(bf[nt][0], bf[nt][1], Bbase + r);
            }
#pragma unroll
            for (int mt = 0; mt < 4; mt++)
#pragma unroll
                for (int nt = 0; nt < 4; nt++)
                    mma16816(acc[mt][nt], af[mt][0], af[mt][1], af[mt][2], af[mt][3],
                             bf[nt][0], bf[nt][1]);
        }
        __syncthreads();   // all warps done reading this stage

        if (kc + 2 < NKc) {
            uint32_t base = sb + (kc & 1) * STAGEB;
            const int koff = (kc + 2) * BK;
#pragma unroll
            for (int i = 0; i < 4; i++) {
                cp_async16(base + sOff[i], gA[i] + koff);
                cp_async16(base + TILEB + sOff[i], gB[i] + koff);
            }
        }
        CP_COMMIT();
    }

#pragma unroll
    for (int mt = 0; mt < 4; mt++) {
        size_t rg = row0 + wm * 64 + mt * 16 + lr;
#pragma unroll
        for (int nt = 0; nt < 4; nt++) {
            size_t cg = (size_t)col0 + wn * 32 + nt * 8 + lc * 2;
            *(float2*)(C + rg * N + cg) = make_float2(acc[mt][nt][0], acc[mt][nt][1]);
            *(float2*)(C + (rg + 8) * N + cg) = make_float2(acc[mt][nt][2], acc[mt][nt][3]);
        }
    }
}

// ---------------- RoPE (in place, fused-qkv layout) ----------------
__global__ void rope_kernel(float* __restrict__ x,
                            const float* __restrict__ cosp,
                            const float* __restrict__ sinp,
                            int nh, int total) {
    int idx = blockIdx.x * blockDim.x + threadIdx.x;
    if (idx >= total) return;
    int d = idx & 63;
    int h = (idx >> 6) % nh;
    int s = idx / (64 * nh);

    float c0 = cosp[s * HD + d];
    float s0 = sinp[s * HD + d];
    float c1 = cosp[s * HD + d + 64];
    float s1 = sinp[s * HD + d + 64];

    float* row = x + (size_t)s * QKVN + h * HD;
    float x0 = row[d];
    float x1 = row[d + 64];
    row[d]      = x0 * c0 - x1 * s0;
    row[d + 64] = x1 * c1 + x0 * s1;
}

// ==================================================================
// Flash attention (tf32 2-term split ~= fp32), fused qkv input.
// Epilogue writes att as interleaved fp16 (out-proj A operand).
// ==================================================================
#define FQ 64
#define FK 64
#define QS 136
#define PS 68
#define FLASH_SMEM ((2 * FQ * QS + FQ * PS) * 4)   // 87040 B

__global__ __launch_bounds__(128) void flash_tc(const float* __restrict__ QKV,
                                                __half* __restrict__ Oh) {
    extern __shared__ __align__(16) float fsm[];
    float* Qs = fsm;
    float* KVs = Qs + FQ * QS;
    float* Ps = KVs + FQ * QS;
    const uint32_t kv_b = smem_u32(KVs);

    const int h = blockIdx.y;
    const int kvh = h >> 2;
    const int qi = gridDim.x - 1 - blockIdx.x;
    const int q0 = qi * FQ;
    const int tid = threadIdx.x;
    const int wid = tid >> 5;
    const int lane = tid & 31;
    const int lr = lane >> 2;
    const int lc = lane & 3;
    const float scale = 0.08838834764831845f;

    const float* Qg = QKV + h * HD;
    const float* Kg = QKV + 4096 + kvh * HD;
    const float* Vg = QKV + 5120 + kvh * HD;

    for (int i = tid; i < FQ * 32; i += 128) {
        int r = i >> 5, c4 = (i & 31) << 2;
        float4 q = *(const float4*)(Qg + (size_t)(q0 + r) * QKVN + c4);
        q.x *= scale; q.y *= scale; q.z *= scale; q.w *= scale;
        *(float4*)(Qs + r * QS + c4) = q;
    }

    float o[16][4];
#pragma unroll
    for (int nt = 0; nt < 16; nt++)
#pragma unroll
        for (int e = 0; e < 4; e++) o[nt][e] = 0.f;
    float m0 = -1e30f, m1 = -1e30f, l0 = 0.f, l1 = 0.f;

    float* Pw = Ps + wid * 16 * PS;

    const int nkt = qi + 1;
    for (int kt = 0; kt < nkt; kt++) {
        const int k0 = kt * FK;

#pragma unroll
        for (int ii = 0; ii < 16; ii++) {
            int i = tid + 128 * ii;
            int r = i >> 5, c4 = (i & 31) << 2;
            cp_async16(kv_b + (uint32_t)((r * QS + c4) * 4),
                       Kg + (size_t)(k0 + r) * QKVN + c4);
        }
        CP_COMMIT();
        CP_WAIT0();
        __syncthreads();

        float sa[8][4];
#pragma unroll
        for (int nt = 0; nt < 8; nt++)
#pragma unroll
            for (int e = 0; e < 4; e++) sa[nt][e] = 0.f;

#pragma unroll 4
        for (int ks = 0; ks < 16; ks++) {
            const int k = ks * 8;
            uint32_t ah[4], al[4];
            {
                const float* p = Qs + (wid * 16 + lr) * QS + k + lc;
                tf32_split(p[0], ah[0], al[0]);
                tf32_split(p[8 * QS], ah[1], al[1]);
                tf32_split(p[4], ah[2], al[2]);
                tf32_split(p[8 * QS + 4], ah[3], al[3]);
            }
#pragma unroll
            for (int nt = 0; nt < 8; nt++) {
                const float* p = KVs + (nt * 8 + lr) * QS + k + lc;
                uint32_t bh[2], bl[2];
                tf32_split(p[0], bh[0], bl[0]);
                tf32_split(p[4], bh[1], bl[1]);
                mma1688(sa[nt], ah, bh);
                mma1688(sa[nt], ah, bl);
                mma1688(sa[nt], al, bh);
            }
        }
        __syncthreads();

#pragma unroll
        for (int ii = 0; ii < 16; ii++) {
            int i = tid + 128 * ii;
            int r = i >> 5, c4 = (i & 31) << 2;
            cp_async16(kv_b + (uint32_t)((r * QS + c4) * 4),
                       Vg + (size_t)(k0 + r) * QKVN + c4);
        }
        CP_COMMIT();

        if (kt == qi) {
            int r0 = q0 + wid * 16 + lr;
#pragma unroll
            for (int nt = 0; nt < 8; nt++) {
                int c = k0 + nt * 8 + lc * 2;
                if (c > r0)         sa[nt][0] = -1e30f;
                if (c + 1 > r0)     sa[nt][1] = -1e30f;
                if (c > r0 + 8)     sa[nt][2] = -1e30f;
                if (c + 1 > r0 + 8) sa[nt][3] = -1e30f;
            }
        }

        float rx0 = -1e30f, rx1 = -1e30f;
#pragma unroll
        for (int nt = 0; nt < 8; nt++) {
            rx0 = fmaxf(rx0, fmaxf(sa[nt][0], sa[nt][1]));
            rx1 = fmaxf(rx1, fmaxf(sa[nt][2], sa[nt][3]));
        }
        rx0 = fmaxf(rx0, __shfl_xor_sync(0xffffffffu, rx0, 1));
        rx0 = fmaxf(rx0, __shfl_xor_sync(0xffffffffu, rx0, 2));
        rx1 = fmaxf(rx1, __shfl_xor_sync(0xffffffffu, rx1, 1));
        rx1 = fmaxf(rx1, __shfl_xor_sync(0xffffffffu, rx1, 2));

        float mn0 = fmaxf(m0, rx0), mn1 = fmaxf(m1, rx1);
        float a0 = __expf(m0 - mn0), a1 = __expf(m1 - mn1);
        m0 = mn0; m1 = mn1;

        float rs0 = 0.f, rs1 = 0.f;
#pragma unroll
        for (int nt = 0; nt < 8; nt++) {
            sa[nt][0] = __expf(sa[nt][0] - mn0);
            sa[nt][1] = __expf(sa[nt][1] - mn0);
            sa[nt][2] = __expf(sa[nt][2] - mn1);
            sa[nt][3] = __expf(sa[nt][3] - mn1);
            rs0 += sa[nt][0] + sa[nt][1];
            rs1 += sa[nt][2] + sa[nt][3];
        }
        rs0 += __shfl_xor_sync(0xffffffffu, rs0, 1);
        rs0 += __shfl_xor_sync(0xffffffffu, rs0, 2);
        rs1 += __shfl_xor_sync(0xffffffffu, rs1, 1);
        rs1 += __shfl_xor_sync(0xffffffffu, rs1, 2);
        l0 = l0 * a0 + rs0;
        l1 = l1 * a1 + rs1;

#pragma unroll
        for (int nt = 0; nt < 16; nt++) {
            o[nt][0] *= a0; o[nt][1] *= a0;
            o[nt][2] *= a1; o[nt][3] *= a1;
        }

#pragma unroll
        for (int nt = 0; nt < 8; nt++) {
            *(float2*)(Pw + lr * PS + nt * 8 + 2 * lc) = make_float2(sa[nt][0], sa[nt][1]);
            *(float2*)(Pw + (lr + 8) * PS + nt * 8 + 2 * lc) = make_float2(sa[nt][2], sa[nt][3]);
        }
        __syncwarp();

        CP_WAIT0();
        __syncthreads();

#pragma unroll 2
        for (int ks = 0; ks < 8; ks++) {
            const int kk = ks * 8;
            uint32_t ah[4], al[4];
            {
                const float* p = Pw + lr * PS + kk + lc;
                tf32_split(p[0], ah[0], al[0]);
                tf32_split(p[8 * PS], ah[1], al[1]);
                tf32_split(p[4], ah[2], al[2]);
                tf32_split(p[8 * PS + 4], ah[3], al[3]);
            }
#pragma unroll
            for (int nt = 0; nt < 16; nt++) {
                const float* p = KVs + (kk + lc) * QS + nt * 8 + lr;
                uint32_t bh[2], bl[2];
                tf32_split(p[0], bh[0], bl[0]);
                tf32_split(p[4 * QS], bh[1], bl[1]);
                mma1688(o[nt], ah, bh);
                mma1688(o[nt], ah, bl);
                mma1688(o[nt], al, bh);
            }
        }
        __syncthreads();
    }

    // epilogue: write interleaved fp16 att rows (group = 16 halves along hid dim)
    float inv0 = 1.0f / l0, inv1 = 1.0f / l1;
    size_t r0 = q0 + wid * 16 + lr;
#pragma unroll
    for (int nt = 0; nt < 16; nt++) {
        int grp = h * 8 + (nt >> 1);               // k16 group in hid dim
        int pos = lc * 4 + (nt & 1) * 2;           // half offset within group
        __half2 v0; v0.x = __float2half_rn(o[nt][0] * inv0);
                    v0.y = __float2half_rn(o[nt][1] * inv0);
        __half2 v1; v1.x = __float2half_rn(o[nt][2] * inv1);
                    v1.y = __float2half_rn(o[nt][3] * inv1);
        *(__half2*)(Oh + r0 * (NH * HD) + grp * 16 + pos) = v0;
        *(__half2*)(Oh + (r0 + 8) * (NH * HD) + grp * 16 + pos) = v1;
    }
}

// ---------------- launch ----------------
extern "C" void kernel_launch(void* const* d_in, const int* in_sizes, int n_in,
                              void* d_out, int out_size) {
    const float* hs   = (const float*)d_in[0];
    const float* cosp = (const float*)d_in[2];
    const float* sinp = (const float*)d_in[3];
    const float* wq   = (const float*)d_in[4];
    const float* wk   = (const float*)d_in[5];
    const float* wv   = (const float*)d_in[6];
    const float* wo   = (const float*)d_in[7];
    float* out = (float*)d_out;

    float* qkv;
    __half *ath, *hsh, *wqh, *wkh, *wvh, *woh;
    cudaGetSymbolAddress((void**)&qkv, g_qkv);
    cudaGetSymbolAddress((void**)&ath, g_att_h);
    cudaGetSymbolAddress((void**)&hsh, g_hs_h);
    cudaGetSymbolAddress((void**)&wqh, g_wq_h);
    cudaGetSymbolAddress((void**)&wkh, g_wk_h);
    cudaGetSymbolAddress((void**)&wvh, g_wv_h);
    cudaGetSymbolAddress((void**)&woh, g_wo_h);

    cudaFuncSetAttribute(gemm_tc,
                         cudaFuncAttributeMaxDynamicSharedMemorySize, GEMM_SMEM);
    cudaFuncSetAttribute(flash_tc,
                         cudaFuncAttributeMaxDynamicSharedMemorySize, FLASH_SMEM);

    const int RT = 256;
    const int ng_hs = S * HID / 16;
    const int ng_wq = NH * HD * HID / 16;
    const int ng_wk = NKV * HD * HID / 16;

    // (0) round hs  (1) round wq  (2) round wk+wv
    round_fp16_kernel<<<(ng_hs + RT - 1) / RT, RT>>>(hs, hsh, ng_hs);
    round_fp16_kernel<<<(ng_wq + RT - 1) / RT, RT>>>(wq, wqh, ng_wq);
    round2_fp16_kernel<<<(2 * ng_wk + RT - 1) / RT, RT>>>(wk, wkh, ng_wk, wv, wvh, ng_wk);
    // (3) fused QKV projection — ncu capture slot
    gemm_tc<<<dim3(QKVN / BN, S / BM), 256, GEMM_SMEM>>>(
        hsh, wqh, wkh, wvh, NH * HD, NH * HD + NKV * HD, qkv, S, QKVN, HID);
    // (4) round wo
    round_fp16_kernel<<<(ng_wq + RT - 1) / RT, RT>>>(wo, woh, ng_wq);
    // (5,6) RoPE on q and k slices
    rope_kernel<<<(S * NH * 64 + 255) / 256, 256>>>(qkv, cosp, sinp, NH, S * NH * 64);
    rope_kernel<<<(S * NKV * 64 + 255) / 256, 256>>>(qkv + 4096, cosp, sinp, NKV, S * NKV * 64);
    // (7) attention
    flash_tc<<<dim3(S / FQ, NH), 128, FLASH_SMEM>>>(qkv, ath);
    // (8) output projection
    gemm_tc<<<dim3(HID / BN, S / BM), 256, GEMM_SMEM>>>(
        ath, woh, woh, woh, HID, HID, out, S, HID, HID);
}

// round 9
// speedup vs baseline: 7.9744x; 1.3227x over previous
#include <cuda_runtime.h>
#include <cuda_fp16.h>
#include <cstdint>

#define S 2048
#define HID 4096
#define NH 32
#define NKV 8
#define HD 128
#define QKVN 6144            // 4096 (q) + 1024 (k) + 1024 (v)

// ---------------- scratch (no allocation allowed) ----------------
__device__ float  g_qkv[(size_t)S * QKVN];
__device__ __half g_att_h[(size_t)S * NH * HD];
__device__ __half g_hs_h[(size_t)S * HID];
__device__ __half g_wq_h[(size_t)NH * HD * HID];
__device__ __half g_wk_h[(size_t)NKV * HD * HID];
__device__ __half g_wv_h[(size_t)NKV * HD * HID];
__device__ __half g_wo_h[(size_t)HID * NH * HD];

// ---------------- helpers ----------------
__device__ __forceinline__ void mma16816(float* d, uint32_t a0, uint32_t a1,
                                         uint32_t a2, uint32_t a3,
                                         uint32_t b0, uint32_t b1) {
    asm volatile(
        "mma.sync.aligned.m16n8k16.row.col.f32.f16.f16.f32 "
        "{%0,%1,%2,%3}, {%4,%5,%6,%7}, {%8,%9}, {%0,%1,%2,%3};"
        : "+f"(d[0]), "+f"(d[1]), "+f"(d[2]), "+f"(d[3])
        : "r"(a0), "r"(a1), "r"(a2), "r"(a3), "r"(b0), "r"(b1));
}

// fp16 2-term split of a float pair: hi2 = rn(x,y), lo2 = rn(residuals)
__device__ __forceinline__ void split2(float x, float y, uint32_t& hi, uint32_t& lo) {
    __half2 h = __floats2half2_rn(x, y);
    float2 r = __half22float2(h);
    __half2 l = __floats2half2_rn(x - r.x, y - r.y);
    hi = *(uint32_t*)&h;
    lo = *(uint32_t*)&l;
}

__device__ __forceinline__ uint32_t smem_u32(const void* p) {
    uint32_t a;
    asm("{ .reg .u64 t; cvta.to.shared.u64 t, %1; cvt.u32.u64 %0, t; }" : "=r"(a) : "l"(p));
    return a;
}

__device__ __forceinline__ void cp_async16(uint32_t saddr, const void* gaddr) {
    asm volatile("cp.async.cg.shared.global [%0], [%1], 16;"
                 :: "r"(saddr), "l"(gaddr) : "memory");
}
#define CP_COMMIT() asm volatile("cp.async.commit_group;" ::: "memory")
#define CP_WAIT1()  asm volatile("cp.async.wait_group 1;" ::: "memory")
#define CP_WAIT0()  asm volatile("cp.async.wait_group 0;" ::: "memory")

__device__ __forceinline__ void lds64(uint32_t& x, uint32_t& y, uint32_t addr) {
    asm volatile("ld.shared.v2.b32 {%0,%1}, [%2];" : "=r"(x), "=r"(y) : "r"(addr));
}

// ---------------- fp16 pre-round with k16-group interleave ----------------
// group of 16 halves stored as pairs: (0,1),(8,9),(2,3),(10,11),(4,5),(12,13),(6,7),(14,15)
__device__ __forceinline__ void round_group(const float* src, __half* dst) {
    float s[16];
#pragma unroll
    for (int i = 0; i < 4; i++) {
        float4 v = ((const float4*)src)[i];
        s[4 * i] = v.x; s[4 * i + 1] = v.y; s[4 * i + 2] = v.z; s[4 * i + 3] = v.w;
    }
    __half2 w[8];
#pragma unroll
    for (int lc = 0; lc < 4; lc++) {
        __half2 a; a.x = __float2half_rn(s[2 * lc]);     a.y = __float2half_rn(s[2 * lc + 1]);
        __half2 b; b.x = __float2half_rn(s[8 + 2 * lc]); b.y = __float2half_rn(s[8 + 2 * lc + 1]);
        w[2 * lc] = a; w[2 * lc + 1] = b;
    }
    uint4* d4 = (uint4*)dst;
    d4[0] = *(uint4*)&w[0];
    d4[1] = *(uint4*)&w[4];
}

__global__ void round_fp16_kernel(const float* __restrict__ in,
                                  __half* __restrict__ out, int ng) {
    int g = blockIdx.x * blockDim.x + threadIdx.x;
    if (g >= ng) return;
    round_group(in + (size_t)g * 16, out + (size_t)g * 16);
}

__global__ void round2_fp16_kernel(const float* __restrict__ inA, __half* __restrict__ outA, int ngA,
                                   const float* __restrict__ inB, __half* __restrict__ outB, int ngB) {
    int g = blockIdx.x * blockDim.x + threadIdx.x;
    if (g < ngA) { round_group(inA + (size_t)g * 16, outA + (size_t)g * 16); return; }
    g -= ngA;
    if (g < ngB) round_group(inB + (size_t)g * 16, outB + (size_t)g * 16);
}

// ==================================================================
// fp16 GEMM: C[M,N] = A[M,K] @ B[N,K]^T  (A,B half, k16-interleaved)
// CTA 128x128, BK=64, 8 warps 2(M)x4(N) -> warp 64x32, 2-stage cp.async.
// ==================================================================
#define BM 128
#define BN 128
#define BK 64
#define ROWB 160
#define TILEB (BM * ROWB)
#define STAGEB (2 * TILEB)
#define GEMM_SMEM (2 * STAGEB)            // 81920 B

__global__ __launch_bounds__(256, 2) void gemm_tc(
        const __half* __restrict__ A,
        const __half* __restrict__ B0, const __half* __restrict__ B1,
        const __half* __restrict__ B2, int nb0, int nb1,
        float* __restrict__ C, int M, int N, int K) {
    extern __shared__ __align__(16) char smem[];
    const uint32_t sb = smem_u32(smem);

    const int tid = threadIdx.x;
    const int wid = tid >> 5;
    const int lane = tid & 31;
    const int wm = wid & 1;
    const int wn = wid >> 1;
    const int lr = lane >> 2;
    const int lc = lane & 3;

    const size_t row0 = (size_t)blockIdx.y * BM;
    const int col0 = blockIdx.x * BN;

    const __half* B;
    int bo;
    if (col0 < nb0)      { B = B0; bo = col0; }
    else if (col0 < nb1) { B = B1; bo = col0 - nb0; }
    else                 { B = B2; bo = col0 - nb1; }

    const __half* gA[4];
    const __half* gB[4];
    uint32_t sOff[4];
#pragma unroll
    for (int i = 0; i < 4; i++) {
        int cid = tid + 256 * i;
        int r = cid >> 3, c = cid & 7;
        gA[i] = A + (row0 + r) * (size_t)K + c * 8;
        gB[i] = B + (size_t)(bo + r) * K + c * 8;
        sOff[i] = (uint32_t)(r * ROWB + c * 16);
    }

    float acc[4][4][4];
#pragma unroll
    for (int mt = 0; mt < 4; mt++)
#pragma unroll
        for (int nt = 0; nt < 4; nt++)
#pragma unroll
            for (int e = 0; e < 4; e++) acc[mt][nt][e] = 0.f;

    const int NKc = K / BK;

#pragma unroll
    for (int st = 0; st < 2; st++) {
        uint32_t base = sb + st * STAGEB;
#pragma unroll
        for (int i = 0; i < 4; i++) {
            cp_async16(base + sOff[i], gA[i] + st * BK);
            cp_async16(base + TILEB + sOff[i], gB[i] + st * BK);
        }
        CP_COMMIT();
    }

    for (int kc = 0; kc < NKc; kc++) {
        CP_WAIT1();
        __syncthreads();

        const uint32_t Abase = sb + (kc & 1) * STAGEB;
        const uint32_t Bbase = Abase + TILEB;

#pragma unroll
        for (int g = 0; g < 4; g++) {
            const uint32_t go = (uint32_t)(g * 32 + lc * 8);
            uint32_t af[4][4], bf[4][2];
#pragma unroll
            for (int mt = 0; mt < 4; mt++) {
                uint32_t r = (uint32_t)((wm * 64 + mt * 16 + lr) * ROWB) + go;
                lds64(af[mt][0], af[mt][2], Abase + r);
                lds64(af[mt][1], af[mt][3], Abase + r + 8 * ROWB);
            }
#pragma unroll
            for (int nt = 0; nt < 4; nt++) {
                uint32_t r = (uint32_t)((wn * 32 + nt * 8 + lr) * ROWB) + go;
                lds64(bf[nt][0], bf[nt][1], Bbase + r);
            }
#pragma unroll
            for (int mt = 0; mt < 4; mt++)
#pragma unroll
                for (int nt = 0; nt < 4; nt++)
                    mma16816(acc[mt][nt], af[mt][0], af[mt][1], af[mt][2], af[mt][3],
                             bf[nt][0], bf[nt][1]);
        }
        __syncthreads();

        if (kc + 2 < NKc) {
            uint32_t base = sb + (kc & 1) * STAGEB;
            const int koff = (kc + 2) * BK;
#pragma unroll
            for (int i = 0; i < 4; i++) {
                cp_async16(base + sOff[i], gA[i] + koff);
                cp_async16(base + TILEB + sOff[i], gB[i] + koff);
            }
        }
        CP_COMMIT();
    }

#pragma unroll
    for (int mt = 0; mt < 4; mt++) {
        size_t rg = row0 + wm * 64 + mt * 16 + lr;
#pragma unroll
        for (int nt = 0; nt < 4; nt++) {
            size_t cg = (size_t)col0 + wn * 32 + nt * 8 + lc * 2;
            *(float2*)(C + rg * N + cg) = make_float2(acc[mt][nt][0], acc[mt][nt][1]);
            *(float2*)(C + (rg + 8) * N + cg) = make_float2(acc[mt][nt][2], acc[mt][nt][3]);
        }
    }
}

// ---------------- RoPE (in place, fused-qkv layout) ----------------
__global__ void rope_kernel(float* __restrict__ x,
                            const float* __restrict__ cosp,
                            const float* __restrict__ sinp,
                            int nh, int total) {
    int idx = blockIdx.x * blockDim.x + threadIdx.x;
    if (idx >= total) return;
    int d = idx & 63;
    int h = (idx >> 6) % nh;
    int s = idx / (64 * nh);

    float c0 = cosp[s * HD + d];
    float s0 = sinp[s * HD + d];
    float c1 = cosp[s * HD + d + 64];
    float s1 = sinp[s * HD + d + 64];

    float* row = x + (size_t)s * QKVN + h * HD;
    float x0 = row[d];
    float x1 = row[d + 64];
    row[d]      = x0 * c0 - x1 * s0;
    row[d + 64] = x1 * c1 + x0 * s1;
}

// ==================================================================
// Flash attention, fp16 m16n8k16 with 2-term split (~fp32 accuracy).
// 128 threads (4 warps), 64 q-rows; warp owns 16 rows.
// Q/K stride 136 (LDS.64 conflict-free), V stride 132 (scalar gather
// conflict-free), P stride 72. K and V share one smem buffer.
// ==================================================================
#define FQ 64
#define FK 64
#define QS 136
#define VSTR 132
#define PS 72
#define KVSZ (FQ * QS)                              // >= FK*VSTR
#define FLASH_SMEM ((2 * FQ * QS + FQ * PS) * 4)    // 88064 B

__global__ __launch_bounds__(128) void flash_tc(const float* __restrict__ QKV,
                                                __half* __restrict__ Oh) {
    extern __shared__ __align__(16) float fsm[];
    float* Qs = fsm;
    float* KVs = Qs + FQ * QS;
    float* Ps = KVs + KVSZ;
    const uint32_t kv_b = smem_u32(KVs);

    const int h = blockIdx.y;
    const int kvh = h >> 2;
    const int qi = gridDim.x - 1 - blockIdx.x;
    const int q0 = qi * FQ;
    const int tid = threadIdx.x;
    const int wid = tid >> 5;
    const int lane = tid & 31;
    const int lr = lane >> 2;
    const int lc = lane & 3;
    const float scale = 0.08838834764831845f;

    const float* Qg = QKV + h * HD;
    const float* Kg = QKV + 4096 + kvh * HD;
    const float* Vg = QKV + 5120 + kvh * HD;

    for (int i = tid; i < FQ * 32; i += 128) {
        int r = i >> 5, c4 = (i & 31) << 2;
        float4 q = *(const float4*)(Qg + (size_t)(q0 + r) * QKVN + c4);
        q.x *= scale; q.y *= scale; q.z *= scale; q.w *= scale;
        *(float4*)(Qs + r * QS + c4) = q;
    }

    float o[16][4];
#pragma unroll
    for (int nt = 0; nt < 16; nt++)
#pragma unroll
        for (int e = 0; e < 4; e++) o[nt][e] = 0.f;
    float m0 = -1e30f, m1 = -1e30f, l0 = 0.f, l1 = 0.f;

    float* Pw = Ps + wid * 16 * PS;

    const int nkt = qi + 1;
    for (int kt = 0; kt < nkt; kt++) {
        const int k0 = kt * FK;

        // ---- K tile load (stride QS) ----
#pragma unroll
        for (int ii = 0; ii < 16; ii++) {
            int i = tid + 128 * ii;
            int r = i >> 5, c4 = (i & 31) << 2;
            cp_async16(kv_b + (uint32_t)((r * QS + c4) * 4),
                       Kg + (size_t)(k0 + r) * QKVN + c4);
        }
        CP_COMMIT();
        CP_WAIT0();
        __syncthreads();

        // ---- QK^T: 64x64, fp16 split (3 MMAs per k16 step) ----
        float sa[8][4];
#pragma unroll
        for (int nt = 0; nt < 8; nt++)
#pragma unroll
            for (int e = 0; e < 4; e++) sa[nt][e] = 0.f;

#pragma unroll 2
        for (int ks = 0; ks < 8; ks++) {
            const int k = ks * 16;
            uint32_t ah[4], al[4];
            {
                const float* p = Qs + (wid * 16 + lr) * QS + k + 2 * lc;
                split2(p[0], p[1], ah[0], al[0]);
                split2(p[8 * QS], p[8 * QS + 1], ah[1], al[1]);
                split2(p[8], p[9], ah[2], al[2]);
                split2(p[8 * QS + 8], p[8 * QS + 9], ah[3], al[3]);
            }
#pragma unroll
            for (int nt = 0; nt < 8; nt++) {
                const float* p = KVs + (nt * 8 + lr) * QS + k + 2 * lc;
                uint32_t bh0, bl0, bh1, bl1;
                split2(p[0], p[1], bh0, bl0);
                split2(p[8], p[9], bh1, bl1);
                mma16816(sa[nt], ah[0], ah[1], ah[2], ah[3], bh0, bh1);
                mma16816(sa[nt], ah[0], ah[1], ah[2], ah[3], bl0, bl1);
                mma16816(sa[nt], al[0], al[1], al[2], al[3], bh0, bh1);
            }
        }
        __syncthreads();   // done reading K

        // ---- V tile load into same buffer (stride VSTR, overlaps softmax) ----
#pragma unroll
        for (int ii = 0; ii < 16; ii++) {
            int i = tid + 128 * ii;
            int r = i >> 5, c4 = (i & 31) << 2;
            cp_async16(kv_b + (uint32_t)((r * VSTR + c4) * 4),
                       Vg + (size_t)(k0 + r) * QKVN + c4);
        }
        CP_COMMIT();

        if (kt == qi) {
            int r0 = q0 + wid * 16 + lr;
#pragma unroll
            for (int nt = 0; nt < 8; nt++) {
                int c = k0 + nt * 8 + lc * 2;
                if (c > r0)         sa[nt][0] = -1e30f;
                if (c + 1 > r0)     sa[nt][1] = -1e30f;
                if (c > r0 + 8)     sa[nt][2] = -1e30f;
                if (c + 1 > r0 + 8) sa[nt][3] = -1e30f;
            }
        }

        float rx0 = -1e30f, rx1 = -1e30f;
#pragma unroll
        for (int nt = 0; nt < 8; nt++) {
            rx0 = fmaxf(rx0, fmaxf(sa[nt][0], sa[nt][1]));
            rx1 = fmaxf(rx1, fmaxf(sa[nt][2], sa[nt][3]));
        }
        rx0 = fmaxf(rx0, __shfl_xor_sync(0xffffffffu, rx0, 1));
        rx0 = fmaxf(rx0, __shfl_xor_sync(0xffffffffu, rx0, 2));
        rx1 = fmaxf(rx1, __shfl_xor_sync(0xffffffffu, rx1, 1));
        rx1 = fmaxf(rx1, __shfl_xor_sync(0xffffffffu, rx1, 2));

        float mn0 = fmaxf(m0, rx0), mn1 = fmaxf(m1, rx1);
        float a0 = __expf(m0 - mn0), a1 = __expf(m1 - mn1);
        m0 = mn0; m1 = mn1;

        float rs0 = 0.f, rs1 = 0.f;
#pragma unroll
        for (int nt = 0; nt < 8; nt++) {
            sa[nt][0] = __expf(sa[nt][0] - mn0);
            sa[nt][1] = __expf(sa[nt][1] - mn0);
            sa[nt][2] = __expf(sa[nt][2] - mn1);
            sa[nt][3] = __expf(sa[nt][3] - mn1);
            rs0 += sa[nt][0] + sa[nt][1];
            rs1 += sa[nt][2] + sa[nt][3];
        }
        rs0 += __shfl_xor_sync(0xffffffffu, rs0, 1);
        rs0 += __shfl_xor_sync(0xffffffffu, rs0, 2);
        rs1 += __shfl_xor_sync(0xffffffffu, rs1, 1);
        rs1 += __shfl_xor_sync(0xffffffffu, rs1, 2);
        l0 = l0 * a0 + rs0;
        l1 = l1 * a1 + rs1;

#pragma unroll
        for (int nt = 0; nt < 16; nt++) {
            o[nt][0] *= a0; o[nt][1] *= a0;
            o[nt][2] *= a1; o[nt][3] *= a1;
        }

#pragma unroll
        for (int nt = 0; nt < 8; nt++) {
            *(float2*)(Pw + lr * PS + nt * 8 + 2 * lc) = make_float2(sa[nt][0], sa[nt][1]);
            *(float2*)(Pw + (lr + 8) * PS + nt * 8 + 2 * lc) = make_float2(sa[nt][2], sa[nt][3]);
        }
        __syncwarp();

        CP_WAIT0();        // V landed
        __syncthreads();

        // ---- PV: O(16x128) += P(16x64) @ V(64x128), fp16 split ----
#pragma unroll
        for (int ks = 0; ks < 4; ks++) {
            const int kk = ks * 16;
            uint32_t ah[4], al[4];
            {
                const float* p = Pw + lr * PS + kk + 2 * lc;
                split2(p[0], p[1], ah[0], al[0]);
                split2(p[8 * PS], p[8 * PS + 1], ah[1], al[1]);
                split2(p[8], p[9], ah[2], al[2]);
                split2(p[8 * PS + 8], p[8 * PS + 9], ah[3], al[3]);
            }
#pragma unroll
            for (int nt = 0; nt < 16; nt++) {
                const float* p = KVs + (kk + 2 * lc) * VSTR + nt * 8 + lr;
                uint32_t bh0, bl0, bh1, bl1;
                split2(p[0], p[VSTR], bh0, bl0);
                split2(p[8 * VSTR], p[9 * VSTR], bh1, bl1);
                mma16816(o[nt], ah[0], ah[1], ah[2], ah[3], bh0, bh1);
                mma16816(o[nt], ah[0], ah[1], ah[2], ah[3], bl0, bl1);
                mma16816(o[nt], al[0], al[1], al[2], al[3], bh0, bh1);
            }
        }
        __syncthreads();
    }

    // epilogue: interleaved fp16 att rows (k16 groups along hid dim)
    float inv0 = 1.0f / l0, inv1 = 1.0f / l1;
    size_t r0 = q0 + wid * 16 + lr;
#pragma unroll
    for (int nt = 0; nt < 16; nt++) {
        int grp = h * 8 + (nt >> 1);
        int pos = lc * 4 + (nt & 1) * 2;
        __half2 v0; v0.x = __float2half_rn(o[nt][0] * inv0);
                    v0.y = __float2half_rn(o[nt][1] * inv0);
        __half2 v1; v1.x = __float2half_rn(o[nt][2] * inv1);
                    v1.y = __float2half_rn(o[nt][3] * inv1);
        *(__half2*)(Oh + r0 * (NH * HD) + grp * 16 + pos) = v0;
        *(__half2*)(Oh + (r0 + 8) * (NH * HD) + grp * 16 + pos) = v1;
    }
}

// ---------------- launch ----------------
extern "C" void kernel_launch(void* const* d_in, const int* in_sizes, int n_in,
                              void* d_out, int out_size) {
    const float* hs   = (const float*)d_in[0];
    const float* cosp = (const float*)d_in[2];
    const float* sinp = (const float*)d_in[3];
    const float* wq   = (const float*)d_in[4];
    const float* wk   = (const float*)d_in[5];
    const float* wv   = (const float*)d_in[6];
    const float* wo   = (const float*)d_in[7];
    float* out = (float*)d_out;

    float* qkv;
    __half *ath, *hsh, *wqh, *wkh, *wvh, *woh;
    cudaGetSymbolAddress((void**)&qkv, g_qkv);
    cudaGetSymbolAddress((void**)&ath, g_att_h);
    cudaGetSymbolAddress((void**)&hsh, g_hs_h);
    cudaGetSymbolAddress((void**)&wqh, g_wq_h);
    cudaGetSymbolAddress((void**)&wkh, g_wk_h);
    cudaGetSymbolAddress((void**)&wvh, g_wv_h);
    cudaGetSymbolAddress((void**)&woh, g_wo_h);

    cudaFuncSetAttribute(gemm_tc,
                         cudaFuncAttributeMaxDynamicSharedMemorySize, GEMM_SMEM);
    cudaFuncSetAttribute(flash_tc,
                         cudaFuncAttributeMaxDynamicSharedMemorySize, FLASH_SMEM);

    const int RT = 256;
    const int ng_hs = S * HID / 16;
    const int ng_wq = NH * HD * HID / 16;
    const int ng_wk = NKV * HD * HID / 16;

    round_fp16_kernel<<<(ng_hs + RT - 1) / RT, RT>>>(hs, hsh, ng_hs);
    round_fp16_kernel<<<(ng_wq + RT - 1) / RT, RT>>>(wq, wqh, ng_wq);
    round2_fp16_kernel<<<(2 * ng_wk + RT - 1) / RT, RT>>>(wk, wkh, ng_wk, wv, wvh, ng_wk);
    // fused QKV projection — ncu capture slot
    gemm_tc<<<dim3(QKVN / BN, S / BM), 256, GEMM_SMEM>>>(
        hsh, wqh, wkh, wvh, NH * HD, NH * HD + NKV * HD, qkv, S, QKVN, HID);
    round_fp16_kernel<<<(ng_wq + RT - 1) / RT, RT>>>(wo, woh, ng_wq);
    rope_kernel<<<(S * NH * 64 + 255) / 256, 256>>>(qkv, cosp, sinp, NH, S * NH * 64);
    rope_kernel<<<(S * NKV * 64 + 255) / 256, 256>>>(qkv + 4096, cosp, sinp, NKV, S * NKV * 64);
    flash_tc<<<dim3(S / FQ, NH), 128, FLASH_SMEM>>>(qkv, ath);
    gemm_tc<<<dim3(HID / BN, S / BM), 256, GEMM_SMEM>>>(
        ath, woh, woh, woh, HID, HID, out, S, HID, HID);
}

// round 10
// speedup vs baseline: 9.0160x; 1.1306x over previous
#include <cuda_runtime.h>
#include <cuda_fp16.h>
#include <cstdint>

#define S 2048
#define HID 4096
#define NH 32
#define NKV 8
#define HD 128
#define QKVN 6144            // 4096 (q) + 1024 (k) + 1024 (v)

// ---------------- scratch (no allocation allowed) ----------------
__device__ float  g_qkv[(size_t)S * QKVN];
__device__ __half g_att_h[(size_t)S * NH * HD];
__device__ __half g_hs_h[(size_t)S * HID];
__device__ __half g_wq_h[(size_t)NH * HD * HID];
__device__ __half g_wk_h[(size_t)NKV * HD * HID];
__device__ __half g_wv_h[(size_t)NKV * HD * HID];
__device__ __half g_wo_h[(size_t)HID * NH * HD];
// pre-split hi/lo planes (k16-interleaved)
__device__ __half g_q_s[(size_t)S * NH * 256];     // [s][h][2][128]
__device__ __half g_k_s[(size_t)S * NKV * 256];    // [s][kvh][2][128]
__device__ __half g_vt[(size_t)NKV * 2 * HD * S];  // [kvh][2][d][s-interleaved]

// ---------------- helpers ----------------
__device__ __forceinline__ void mma16816(float* d, uint32_t a0, uint32_t a1,
                                         uint32_t a2, uint32_t a3,
                                         uint32_t b0, uint32_t b1) {
    asm volatile(
        "mma.sync.aligned.m16n8k16.row.col.f32.f16.f16.f32 "
        "{%0,%1,%2,%3}, {%4,%5,%6,%7}, {%8,%9}, {%0,%1,%2,%3};"
        : "+f"(d[0]), "+f"(d[1]), "+f"(d[2]), "+f"(d[3])
        : "r"(a0), "r"(a1), "r"(a2), "r"(a3), "r"(b0), "r"(b1));
}

__device__ __forceinline__ void split2(float x, float y, uint32_t& hi, uint32_t& lo) {
    __half2 h = __floats2half2_rn(x, y);
    float2 r = __half22float2(h);
    __half2 l = __floats2half2_rn(x - r.x, y - r.y);
    hi = *(uint32_t*)&h;
    lo = *(uint32_t*)&l;
}

__device__ __forceinline__ uint32_t smem_u32(const void* p) {
    uint32_t a;
    asm("{ .reg .u64 t; cvta.to.shared.u64 t, %1; cvt.u32.u64 %0, t; }" : "=r"(a) : "l"(p));
    return a;
}

__device__ __forceinline__ void cp_async16(uint32_t saddr, const void* gaddr) {
    asm volatile("cp.async.cg.shared.global [%0], [%1], 16;"
                 :: "r"(saddr), "l"(gaddr) : "memory");
}
#define CP_COMMIT() asm volatile("cp.async.commit_group;" ::: "memory")
#define CP_WAIT1()  asm volatile("cp.async.wait_group 1;" ::: "memory")
#define CP_WAIT0()  asm volatile("cp.async.wait_group 0;" ::: "memory")

__device__ __forceinline__ void lds64(uint32_t& x, uint32_t& y, uint32_t addr) {
    asm volatile("ld.shared.v2.b32 {%0,%1}, [%2];" : "=r"(x), "=r"(y) : "r"(addr));
}

// ---------------- fp16 pre-round with k16-group interleave ----------------
__device__ __forceinline__ void round_group(const float* src, __half* dst) {
    float s[16];
#pragma unroll
    for (int i = 0; i < 4; i++) {
        float4 v = ((const float4*)src)[i];
        s[4 * i] = v.x; s[4 * i + 1] = v.y; s[4 * i + 2] = v.z; s[4 * i + 3] = v.w;
    }
    __half2 w[8];
#pragma unroll
    for (int lc = 0; lc < 4; lc++) {
        __half2 a; a.x = __float2half_rn(s[2 * lc]);     a.y = __float2half_rn(s[2 * lc + 1]);
        __half2 b; b.x = __float2half_rn(s[8 + 2 * lc]); b.y = __float2half_rn(s[8 + 2 * lc + 1]);
        w[2 * lc] = a; w[2 * lc + 1] = b;
    }
    uint4* d4 = (uint4*)dst;
    d4[0] = *(uint4*)&w[0];
    d4[1] = *(uint4*)&w[4];
}

__global__ void round_fp16_kernel(const float* __restrict__ in,
                                  __half* __restrict__ out, int ng) {
    int g = blockIdx.x * blockDim.x + threadIdx.x;
    if (g >= ng) return;
    round_group(in + (size_t)g * 16, out + (size_t)g * 16);
}

__global__ void round2_fp16_kernel(const float* __restrict__ inA, __half* __restrict__ outA, int ngA,
                                   const float* __restrict__ inB, __half* __restrict__ outB, int ngB) {
    int g = blockIdx.x * blockDim.x + threadIdx.x;
    if (g < ngA) { round_group(inA + (size_t)g * 16, outA + (size_t)g * 16); return; }
    g -= ngA;
    if (g < ngB) round_group(inB + (size_t)g * 16, outB + (size_t)g * 16);
}

// ==================================================================
// fp16 GEMM (unchanged from R9): CTA 128x128, BK=64, warp 64x32.
// ==================================================================
#define BM 128
#define BN 128
#define BK 64
#define ROWB 160
#define TILEB (BM * ROWB)
#define STAGEB (2 * TILEB)
#define GEMM_SMEM (2 * STAGEB)            // 81920 B

__global__ __launch_bounds__(256, 2) void gemm_tc(
        const __half* __restrict__ A,
        const __half* __restrict__ B0, const __half* __restrict__ B1,
        const __half* __restrict__ B2, int nb0, int nb1,
        float* __restrict__ C, int M, int N, int K) {
    extern __shared__ __align__(16) char smem[];
    const uint32_t sb = smem_u32(smem);

    const int tid = threadIdx.x;
    const int wid = tid >> 5;
    const int lane = tid & 31;
    const int wm = wid & 1;
    const int wn = wid >> 1;
    const int lr = lane >> 2;
    const int lc = lane & 3;

    const size_t row0 = (size_t)blockIdx.y * BM;
    const int col0 = blockIdx.x * BN;

    const __half* B;
    int bo;
    if (col0 < nb0)      { B = B0; bo = col0; }
    else if (col0 < nb1) { B = B1; bo = col0 - nb0; }
    else                 { B = B2; bo = col0 - nb1; }

    const __half* gA[4];
    const __half* gB[4];
    uint32_t sOff[4];
#pragma unroll
    for (int i = 0; i < 4; i++) {
        int cid = tid + 256 * i;
        int r = cid >> 3, c = cid & 7;
        gA[i] = A + (row0 + r) * (size_t)K + c * 8;
        gB[i] = B + (size_t)(bo + r) * K + c * 8;
        sOff[i] = (uint32_t)(r * ROWB + c * 16);
    }

    float acc[4][4][4];
#pragma unroll
    for (int mt = 0; mt < 4; mt++)
#pragma unroll
        for (int nt = 0; nt < 4; nt++)
#pragma unroll
            for (int e = 0; e < 4; e++) acc[mt][nt][e] = 0.f;

    const int NKc = K / BK;

#pragma unroll
    for (int st = 0; st < 2; st++) {
        uint32_t base = sb + st * STAGEB;
#pragma unroll
        for (int i = 0; i < 4; i++) {
            cp_async16(base + sOff[i], gA[i] + st * BK);
            cp_async16(base + TILEB + sOff[i], gB[i] + st * BK);
        }
        CP_COMMIT();
    }

    for (int kc = 0; kc < NKc; kc++) {
        CP_WAIT1();
        __syncthreads();

        const uint32_t Abase = sb + (kc & 1) * STAGEB;
        const uint32_t Bbase = Abase + TILEB;

#pragma unroll
        for (int g = 0; g < 4; g++) {
            const uint32_t go = (uint32_t)(g * 32 + lc * 8);
            uint32_t af[4][4], bf[4][2];
#pragma unroll
            for (int mt = 0; mt < 4; mt++) {
                uint32_t r = (uint32_t)((wm * 64 + mt * 16 + lr) * ROWB) + go;
                lds64(af[mt][0], af[mt][2], Abase + r);
                lds64(af[mt][1], af[mt][3], Abase + r + 8 * ROWB);
            }
#pragma unroll
            for (int nt = 0; nt < 4; nt++) {
                uint32_t r = (uint32_t)((wn * 32 + nt * 8 + lr) * ROWB) + go;
                lds64(bf[nt][0], bf[nt][1], Bbase + r);
            }
#pragma unroll
            for (int mt = 0; mt < 4; mt++)
#pragma unroll
                for (int nt = 0; nt < 4; nt++)
                    mma16816(acc[mt][nt], af[mt][0], af[mt][1], af[mt][2], af[mt][3],
                             bf[nt][0], bf[nt][1]);
        }
        __syncthreads();

        if (kc + 2 < NKc) {
            uint32_t base = sb + (kc & 1) * STAGEB;
            const int koff = (kc + 2) * BK;
#pragma unroll
            for (int i = 0; i < 4; i++) {
                cp_async16(base + sOff[i], gA[i] + koff);
                cp_async16(base + TILEB + sOff[i], gB[i] + koff);
            }
        }
        CP_COMMIT();
    }

#pragma unroll
    for (int mt = 0; mt < 4; mt++) {
        size_t rg = row0 + wm * 64 + mt * 16 + lr;
#pragma unroll
        for (int nt = 0; nt < 4; nt++) {
            size_t cg = (size_t)col0 + wn * 32 + nt * 8 + lc * 2;
            *(float2*)(C + rg * N + cg) = make_float2(acc[mt][nt][0], acc[mt][nt][1]);
            *(float2*)(C + (rg + 8) * N + cg) = make_float2(acc[mt][nt][2], acc[mt][nt][3]);
        }
    }
}

// ==================================================================
// RoPE + fp16 hi/lo split (k16-interleaved), warp per (s,h) row.
// scale folded into Q.
// ==================================================================
__global__ void rope_split_kernel(const float* __restrict__ src,
                                  const float* __restrict__ cosp,
                                  const float* __restrict__ sinp,
                                  __half* __restrict__ dst,
                                  int nh, float scale) {
    int wpb = blockDim.x >> 5;
    int idx = blockIdx.x * wpb + (threadIdx.x >> 5);
    int lane = threadIdx.x & 31;
    int s = idx / nh, h = idx - s * nh;
    int d0 = 4 * lane;

    const float* row = src + (size_t)s * QKVN + h * HD;
    float4 x = *(const float4*)(row + d0);
    float4 c = *(const float4*)(cosp + s * HD + d0);
    float4 sn = *(const float4*)(sinp + s * HD + d0);
    float xs[4] = {x.x, x.y, x.z, x.w};
    float cs[4] = {c.x, c.y, c.z, c.w};
    float ss[4] = {sn.x, sn.y, sn.z, sn.w};
    float sign = (lane < 16) ? -1.f : 1.f;
    float out[4];
#pragma unroll
    for (int j = 0; j < 4; j++) {
        float p = __shfl_xor_sync(0xffffffffu, xs[j], 16);
        out[j] = (xs[j] * cs[j] + sign * p * ss[j]) * scale;
    }

    int g = lane >> 2;
    int e = 4 * (lane & 3);
    int s0 = (e < 8) ? e : e - 7;
    int s1 = (e + 2 < 8) ? e + 2 : e - 5;

    __half2 h0 = __floats2half2_rn(out[0], out[1]);
    __half2 h1 = __floats2half2_rn(out[2], out[3]);
    float2 r0 = __half22float2(h0), r1 = __half22float2(h1);
    __half2 l0 = __floats2half2_rn(out[0] - r0.x, out[1] - r0.y);
    __half2 l1 = __floats2half2_rn(out[2] - r1.x, out[3] - r1.y);

    __half2* dh = (__half2*)dst;
    size_t base = (size_t)(s * nh + h) * 128;   // half2 units (2 planes x 64)
    dh[base + g * 8 + s0] = h0;
    dh[base + g * 8 + s1] = h1;
    dh[base + 64 + g * 8 + s0] = l0;
    dh[base + 64 + g * 8 + s1] = l1;
}

// ==================================================================
// V transpose + split: V[s][d] -> V^T[d][s] hi/lo planes, s-interleaved.
// grid (S/64, NKV), 256 threads.
// ==================================================================
__global__ __launch_bounds__(256) void convert_v_kernel(const float* __restrict__ qkv,
                                                        __half* __restrict__ vt) {
    __shared__ float vsm[64][132];
    int s0 = blockIdx.x * 64;
    int kvh = blockIdx.y;
    int tid = threadIdx.x;

    for (int i = tid; i < 64 * 32; i += 256) {
        int r = i >> 5, c4 = (i & 31) * 4;
        float4 v = *(const float4*)(qkv + (size_t)(s0 + r) * QKVN + 5120 + kvh * HD + c4);
        vsm[r][c4] = v.x; vsm[r][c4 + 1] = v.y; vsm[r][c4 + 2] = v.z; vsm[r][c4 + 3] = v.w;
    }
    __syncthreads();

    int d = tid >> 1, hp = tid & 1;
    float v[32];
#pragma unroll
    for (int j = 0; j < 32; j++) v[j] = vsm[32 * hp + j][d];

#pragma unroll
    for (int g2 = 0; g2 < 2; g2++) {
        __half2 hi[8], lo[8];
#pragma unroll
        for (int slot = 0; slot < 8; slot++) {
            int e = (slot & 1) ? slot + 7 : slot;
            float x = v[g2 * 16 + e], y = v[g2 * 16 + e + 1];
            __half2 hh = __floats2half2_rn(x, y);
            float2 r = __half22float2(hh);
            hi[slot] = hh;
            lo[slot] = __floats2half2_rn(x - r.x, y - r.y);
        }
        int kbase = s0 + (2 * hp + g2) * 16;
        __half2* dhi = (__half2*)vt + ((((size_t)kvh * 2 + 0) * HD + d) * S + kbase) / 2;
        __half2* dlo = (__half2*)vt + ((((size_t)kvh * 2 + 1) * HD + d) * S + kbase) / 2;
#pragma unroll
        for (int slot = 0; slot < 8; slot++) { dhi[slot] = hi[slot]; dlo[slot] = lo[slot]; }
    }
}

// ==================================================================
// Flash attention, fp16 split MMA with PRE-SPLIT Q/K/V planes.
// 128 threads (4 warps), 64 q-rows; warp owns 16 rows.
// ==================================================================
#define FQ 64
#define FK 64
#define QROWB 288                      // 72 words ≡ 8 mod 32
#define VROWB 160                      // 40 words ≡ 8 mod 32
#define Q_PLANE (64 * QROWB)           // 18432
#define KV_OFF (2 * Q_PLANE)           // 36864
#define KV_BYTES 40960                 // max(K planes 36864, V^T planes 40960)
#define P_OFF (KV_OFF + KV_BYTES)      // 77824
#define PS 72
#define FLASH_SMEM (P_OFF + 64 * PS * 4)   // 96256 B

__global__ __launch_bounds__(128) void flash_tc(const __half* __restrict__ Qsg,
                                                const __half* __restrict__ Ksg,
                                                const __half* __restrict__ VTg,
                                                __half* __restrict__ Oh) {
    extern __shared__ __align__(16) char fsm[];
    const uint32_t qhi_b = smem_u32(fsm);
    const uint32_t qlo_b = qhi_b + Q_PLANE;
    const uint32_t kv_b  = qhi_b + KV_OFF;       // Khi or VThi
    const uint32_t klo_b = kv_b + 64 * QROWB;
    const uint32_t vlo_b = kv_b + 128 * VROWB;
    float* Ps = (float*)(fsm + P_OFF);

    const int h = blockIdx.y;
    const int kvh = h >> 2;
    const int qi = gridDim.x - 1 - blockIdx.x;
    const int q0 = qi * FQ;
    const int tid = threadIdx.x;
    const int wid = tid >> 5;
    const int lane = tid & 31;
    const int lr = lane >> 2;
    const int lc = lane & 3;

    // Q tile load (pre-scaled, pre-split): 2048 chunks
#pragma unroll
    for (int ii = 0; ii < 16; ii++) {
        int i = tid + 128 * ii;
        int r = i >> 5, c = i & 31;
        int plane = c >> 4, j = c & 15;
        cp_async16((plane ? qlo_b : qhi_b) + (uint32_t)(r * QROWB + j * 16),
                   Qsg + ((size_t)(q0 + r) * NH + h) * 256 + plane * 128 + j * 8);
    }
    CP_COMMIT();

    float o[16][4];
#pragma unroll
    for (int nt = 0; nt < 16; nt++)
#pragma unroll
        for (int e = 0; e < 4; e++) o[nt][e] = 0.f;
    float m0 = -1e30f, m1 = -1e30f, l0v = 0.f, l1v = 0.f;

    float* Pw = Ps + wid * 16 * PS;

    const int nkt = qi + 1;
    for (int kt = 0; kt < nkt; kt++) {
        const int k0 = kt * FK;

        // ---- K tile (split planes) ----
#pragma unroll
        for (int ii = 0; ii < 16; ii++) {
            int i = tid + 128 * ii;
            int r = i >> 5, c = i & 31;
            int plane = c >> 4, j = c & 15;
            cp_async16((plane ? klo_b : kv_b) + (uint32_t)(r * QROWB + j * 16),
                       Ksg + ((size_t)(k0 + r) * NKV + kvh) * 256 + plane * 128 + j * 8);
        }
        CP_COMMIT();
        CP_WAIT0();
        __syncthreads();

        // ---- QK^T: 64x64, hi/lo from smem planes ----
        float sa[8][4];
#pragma unroll
        for (int nt = 0; nt < 8; nt++)
#pragma unroll
            for (int e = 0; e < 4; e++) sa[nt][e] = 0.f;

#pragma unroll 2
        for (int ks = 0; ks < 8; ks++) {
            const uint32_t go = (uint32_t)(ks * 32 + lc * 8);
            uint32_t ah[4], al[4];
            {
                uint32_t r = (uint32_t)((wid * 16 + lr) * QROWB) + go;
                lds64(ah[0], ah[2], qhi_b + r);
                lds64(ah[1], ah[3], qhi_b + r + 8 * QROWB);
                lds64(al[0], al[2], qlo_b + r);
                lds64(al[1], al[3], qlo_b + r + 8 * QROWB);
            }
#pragma unroll
            for (int nt = 0; nt < 8; nt++) {
                uint32_t r = (uint32_t)((nt * 8 + lr) * QROWB) + go;
                uint32_t bh0, bh1, bl0, bl1;
                lds64(bh0, bh1, kv_b + r);
                lds64(bl0, bl1, klo_b + r);
                mma16816(sa[nt], ah[0], ah[1], ah[2], ah[3], bh0, bh1);
                mma16816(sa[nt], ah[0], ah[1], ah[2], ah[3], bl0, bl1);
                mma16816(sa[nt], al[0], al[1], al[2], al[3], bh0, bh1);
            }
        }
        __syncthreads();   // done reading K

        // ---- V^T tile load into same buffer (overlaps softmax) ----
#pragma unroll
        for (int ii = 0; ii < 16; ii++) {
            int i = tid + 128 * ii;
            int plane = i >> 10;
            int rem = i & 1023;
            int d = rem >> 3, j = rem & 7;
            cp_async16((plane ? vlo_b : kv_b) + (uint32_t)(d * VROWB + j * 16),
                       VTg + (((size_t)kvh * 2 + plane) * HD + d) * S + k0 + j * 8);
        }
        CP_COMMIT();

        if (kt == qi) {
            int r0 = q0 + wid * 16 + lr;
#pragma unroll
            for (int nt = 0; nt < 8; nt++) {
                int c = k0 + nt * 8 + lc * 2;
                if (c > r0)         sa[nt][0] = -1e30f;
                if (c + 1 > r0)     sa[nt][1] = -1e30f;
                if (c > r0 + 8)     sa[nt][2] = -1e30f;
                if (c + 1 > r0 + 8) sa[nt][3] = -1e30f;
            }
        }

        float rx0 = -1e30f, rx1 = -1e30f;
#pragma unroll
        for (int nt = 0; nt < 8; nt++) {
            rx0 = fmaxf(rx0, fmaxf(sa[nt][0], sa[nt][1]));
            rx1 = fmaxf(rx1, fmaxf(sa[nt][2], sa[nt][3]));
        }
        rx0 = fmaxf(rx0, __shfl_xor_sync(0xffffffffu, rx0, 1));
        rx0 = fmaxf(rx0, __shfl_xor_sync(0xffffffffu, rx0, 2));
        rx1 = fmaxf(rx1, __shfl_xor_sync(0xffffffffu, rx1, 1));
        rx1 = fmaxf(rx1, __shfl_xor_sync(0xffffffffu, rx1, 2));

        float mn0 = fmaxf(m0, rx0), mn1 = fmaxf(m1, rx1);
        float a0 = __expf(m0 - mn0), a1 = __expf(m1 - mn1);
        m0 = mn0; m1 = mn1;

        float rs0 = 0.f, rs1 = 0.f;
#pragma unroll
        for (int nt = 0; nt < 8; nt++) {
            sa[nt][0] = __expf(sa[nt][0] - mn0);
            sa[nt][1] = __expf(sa[nt][1] - mn0);
            sa[nt][2] = __expf(sa[nt][2] - mn1);
            sa[nt][3] = __expf(sa[nt][3] - mn1);
            rs0 += sa[nt][0] + sa[nt][1];
            rs1 += sa[nt][2] + sa[nt][3];
        }
        rs0 += __shfl_xor_sync(0xffffffffu, rs0, 1);
        rs0 += __shfl_xor_sync(0xffffffffu, rs0, 2);
        rs1 += __shfl_xor_sync(0xffffffffu, rs1, 1);
        rs1 += __shfl_xor_sync(0xffffffffu, rs1, 2);
        l0v = l0v * a0 + rs0;
        l1v = l1v * a1 + rs1;

#pragma unroll
        for (int nt = 0; nt < 16; nt++) {
            o[nt][0] *= a0; o[nt][1] *= a0;
            o[nt][2] *= a1; o[nt][3] *= a1;
        }

#pragma unroll
        for (int nt = 0; nt < 8; nt++) {
            *(float2*)(Pw + lr * PS + nt * 8 + 2 * lc) = make_float2(sa[nt][0], sa[nt][1]);
            *(float2*)(Pw + (lr + 8) * PS + nt * 8 + 2 * lc) = make_float2(sa[nt][2], sa[nt][3]);
        }
        __syncwarp();

        CP_WAIT0();        // V^T landed
        __syncthreads();

        // ---- PV: O(16x128) += P(16x64) @ V(64x128) ----
#pragma unroll
        for (int ks = 0; ks < 4; ks++) {
            const int kk = ks * 16;
            uint32_t ah[4], al[4];
            {
                const float* p = Pw + lr * PS + kk + 2 * lc;
                split2(p[0], p[1], ah[0], al[0]);
                split2(p[8 * PS], p[8 * PS + 1], ah[1], al[1]);
                split2(p[8], p[9], ah[2], al[2]);
                split2(p[8 * PS + 8], p[8 * PS + 9], ah[3], al[3]);
            }
            const uint32_t go = (uint32_t)(ks * 32 + lc * 8);
#pragma unroll
            for (int nt = 0; nt < 16; nt++) {
                uint32_t r = (uint32_t)((nt * 8 + lr) * VROWB) + go;
                uint32_t bh0, bh1, bl0, bl1;
                lds64(bh0, bh1, kv_b + r);
                lds64(bl0, bl1, vlo_b + r);
                mma16816(o[nt], ah[0], ah[1], ah[2], ah[3], bh0, bh1);
                mma16816(o[nt], ah[0], ah[1], ah[2], ah[3], bl0, bl1);
                mma16816(o[nt], al[0], al[1], al[2], al[3], bh0, bh1);
            }
        }
        __syncthreads();
    }

    // epilogue: interleaved fp16 att rows (k16 groups along hid dim)
    float inv0 = 1.0f / l0v, inv1 = 1.0f / l1v;
    size_t r0 = q0 + wid * 16 + lr;
#pragma unroll
    for (int nt = 0; nt < 16; nt++) {
        int grp = h * 8 + (nt >> 1);
        int pos = lc * 4 + (nt & 1) * 2;
        __half2 v0; v0.x = __float2half_rn(o[nt][0] * inv0);
                    v0.y = __float2half_rn(o[nt][1] * inv0);
        __half2 v1; v1.x = __float2half_rn(o[nt][2] * inv1);
                    v1.y = __float2half_rn(o[nt][3] * inv1);
        *(__half2*)(Oh + r0 * (NH * HD) + grp * 16 + pos) = v0;
        *(__half2*)(Oh + (r0 + 8) * (NH * HD) + grp * 16 + pos) = v1;
    }
}

// ---------------- launch ----------------
extern "C" void kernel_launch(void* const* d_in, const int* in_sizes, int n_in,
                              void* d_out, int out_size) {
    const float* hs   = (const float*)d_in[0];
    const float* cosp = (const float*)d_in[2];
    const float* sinp = (const float*)d_in[3];
    const float* wq   = (const float*)d_in[4];
    const float* wk   = (const float*)d_in[5];
    const float* wv   = (const float*)d_in[6];
    const float* wo   = (const float*)d_in[7];
    float* out = (float*)d_out;

    float* qkv;
    __half *ath, *hsh, *wqh, *wkh, *wvh, *woh, *qs, *ks, *vt;
    cudaGetSymbolAddress((void**)&qkv, g_qkv);
    cudaGetSymbolAddress((void**)&ath, g_att_h);
    cudaGetSymbolAddress((void**)&hsh, g_hs_h);
    cudaGetSymbolAddress((void**)&wqh, g_wq_h);
    cudaGetSymbolAddress((void**)&wkh, g_wk_h);
    cudaGetSymbolAddress((void**)&wvh, g_wv_h);
    cudaGetSymbolAddress((void**)&woh, g_wo_h);
    cudaGetSymbolAddress((void**)&qs, g_q_s);
    cudaGetSymbolAddress((void**)&ks, g_k_s);
    cudaGetSymbolAddress((void**)&vt, g_vt);

    cudaFuncSetAttribute(gemm_tc,
                         cudaFuncAttributeMaxDynamicSharedMemorySize, GEMM_SMEM);
    cudaFuncSetAttribute(flash_tc,
                         cudaFuncAttributeMaxDynamicSharedMemorySize, FLASH_SMEM);

    const int RT = 256;
    const int ng_hs = S * HID / 16;
    const int ng_wq = NH * HD * HID / 16;
    const int ng_wk = NKV * HD * HID / 16;
    const float scale = 0.08838834764831845f;

    round_fp16_kernel<<<(ng_hs + RT - 1) / RT, RT>>>(hs, hsh, ng_hs);
    round_fp16_kernel<<<(ng_wq + RT - 1) / RT, RT>>>(wq, wqh, ng_wq);
    round2_fp16_kernel<<<(2 * ng_wk + RT - 1) / RT, RT>>>(wk, wkh, ng_wk, wv, wvh, ng_wk);
    // fused QKV projection — ncu capture slot
    gemm_tc<<<dim3(QKVN / BN, S / BM), 256, GEMM_SMEM>>>(
        hsh, wqh, wkh, wvh, NH * HD, NH * HD + NKV * HD, qkv, S, QKVN, HID);
    round_fp16_kernel<<<(ng_wq + RT - 1) / RT, RT>>>(wo, woh, ng_wq);
    // rope + split (Q scaled), K split, V transpose+split
    rope_split_kernel<<<S * NH / 8, 256>>>(qkv, cosp, sinp, qs, NH, scale);
    rope_split_kernel<<<S * NKV / 8, 256>>>(qkv + 4096, cosp, sinp, ks, NKV, 1.0f);
    convert_v_kernel<<<dim3(S / 64, NKV), 256>>>(qkv, vt);
    // attention
    flash_tc<<<dim3(S / FQ, NH), 128, FLASH_SMEM>>>(qs, ks, vt, ath);
    // output projection
    gemm_tc<<<dim3(HID / BN, S / BM), 256, GEMM_SMEM>>>(
        ath, woh, woh, woh, HID, HID, out, S, HID, HID);
}

// round 11
// speedup vs baseline: 9.2614x; 1.0272x over previous
#include <cuda_runtime.h>
#include <cuda_fp16.h>
#include <cstdint>

#define S 2048
#define HID 4096
#define NH 32
#define NKV 8
#define HD 128
#define QKVN 6144            // 4096 (q) + 1024 (k) + 1024 (v)

// ---------------- scratch (no allocation allowed) ----------------
__device__ float  g_qkv[(size_t)S * QKVN];
__device__ __half g_att_h[(size_t)S * NH * HD];
__device__ __half g_hs_h[(size_t)S * HID];
__device__ __half g_wq_h[(size_t)NH * HD * HID];
__device__ __half g_wk_h[(size_t)NKV * HD * HID];
__device__ __half g_wv_h[(size_t)NKV * HD * HID];
__device__ __half g_wo_h[(size_t)HID * NH * HD];
// flash pre-split hi/lo planes (k16-interleaved, flash-private layout)
__device__ __half g_q_s[(size_t)S * NH * 256];     // [s][h][2][128]
__device__ __half g_k_s[(size_t)S * NKV * 256];    // [s][kvh][2][128]
__device__ __half g_vt[(size_t)NKV * 2 * HD * S];  // [kvh][2][d][s-interleaved]

// ---------------- helpers ----------------
__device__ __forceinline__ void mma16816(float* d, uint32_t a0, uint32_t a1,
                                         uint32_t a2, uint32_t a3,
                                         uint32_t b0, uint32_t b1) {
    asm volatile(
        "mma.sync.aligned.m16n8k16.row.col.f32.f16.f16.f32 "
        "{%0,%1,%2,%3}, {%4,%5,%6,%7}, {%8,%9}, {%0,%1,%2,%3};"
        : "+f"(d[0]), "+f"(d[1]), "+f"(d[2]), "+f"(d[3])
        : "r"(a0), "r"(a1), "r"(a2), "r"(a3), "r"(b0), "r"(b1));
}

__device__ __forceinline__ void ldsm_x4(uint32_t& r0, uint32_t& r1,
                                        uint32_t& r2, uint32_t& r3, uint32_t addr) {
    asm volatile("ldmatrix.sync.aligned.m8n8.x4.shared.b16 {%0,%1,%2,%3}, [%4];"
                 : "=r"(r0), "=r"(r1), "=r"(r2), "=r"(r3) : "r"(addr));
}

__device__ __forceinline__ void split2(float x, float y, uint32_t& hi, uint32_t& lo) {
    __half2 h = __floats2half2_rn(x, y);
    float2 r = __half22float2(h);
    __half2 l = __floats2half2_rn(x - r.x, y - r.y);
    hi = *(uint32_t*)&h;
    lo = *(uint32_t*)&l;
}

__device__ __forceinline__ uint32_t smem_u32(const void* p) {
    uint32_t a;
    asm("{ .reg .u64 t; cvta.to.shared.u64 t, %1; cvt.u32.u64 %0, t; }" : "=r"(a) : "l"(p));
    return a;
}

__device__ __forceinline__ void cp_async16(uint32_t saddr, const void* gaddr) {
    asm volatile("cp.async.cg.shared.global [%0], [%1], 16;"
                 :: "r"(saddr), "l"(gaddr) : "memory");
}
#define CP_COMMIT() asm volatile("cp.async.commit_group;" ::: "memory")
#define CP_WAIT1()  asm volatile("cp.async.wait_group 1;" ::: "memory")
#define CP_WAIT0()  asm volatile("cp.async.wait_group 0;" ::: "memory")

__device__ __forceinline__ void lds64(uint32_t& x, uint32_t& y, uint32_t addr) {
    asm volatile("ld.shared.v2.b32 {%0,%1}, [%2];" : "=r"(x), "=r"(y) : "r"(addr));
}

// ---------------- plain fp16 conversion (8 floats -> 8 halves / thread) ----------------
__global__ void round_fp16_kernel(const float* __restrict__ in,
                                  __half* __restrict__ out, int n8) {
    int i = blockIdx.x * blockDim.x + threadIdx.x;
    if (i >= n8) return;
    float4 a = ((const float4*)in)[2 * i];
    float4 b = ((const float4*)in)[2 * i + 1];
    __half2 h0 = __floats2half2_rn(a.x, a.y);
    __half2 h1 = __floats2half2_rn(a.z, a.w);
    __half2 h2 = __floats2half2_rn(b.x, b.y);
    __half2 h3 = __floats2half2_rn(b.z, b.w);
    uint4 o;
    o.x = *(uint32_t*)&h0; o.y = *(uint32_t*)&h1;
    o.z = *(uint32_t*)&h2; o.w = *(uint32_t*)&h3;
    ((uint4*)out)[i] = o;
}

__global__ void round2_fp16_kernel(const float* __restrict__ inA, __half* __restrict__ outA, int n8A,
                                   const float* __restrict__ inB, __half* __restrict__ outB, int n8B) {
    int i = blockIdx.x * blockDim.x + threadIdx.x;
    const float4* src;
    uint4* dst;
    int j;
    if (i < n8A) { src = (const float4*)inA; dst = (uint4*)outA; j = i; }
    else { j = i - n8A; if (j >= n8B) return; src = (const float4*)inB; dst = (uint4*)outB; }
    float4 a = src[2 * j], b = src[2 * j + 1];
    __half2 h0 = __floats2half2_rn(a.x, a.y);
    __half2 h1 = __floats2half2_rn(a.z, a.w);
    __half2 h2 = __floats2half2_rn(b.x, b.y);
    __half2 h3 = __floats2half2_rn(b.z, b.w);
    uint4 o;
    o.x = *(uint32_t*)&h0; o.y = *(uint32_t*)&h1;
    o.z = *(uint32_t*)&h2; o.w = *(uint32_t*)&h3;
    dst[j] = o;
}

// ==================================================================
// fp16 GEMM v3: C[M,N] = A[M,K] @ B[N,K]^T  (A,B plain half, K-contig)
// CTA 128x128, BK=64, 8 warps 2(M)x4(N) -> warp 64x32, 2-stage cp.async.
// Fragments via ldmatrix.x4. Row = 64 halves padded to 144B
// (36 words ≡ 4 mod 32 -> LDSM 8-row groups hit banks {0,4,...,28}).
// ==================================================================
#define BM 128
#define BN 128
#define BK 64
#define ROWB 144
#define TILEB (BM * ROWB)                 // 18432
#define STAGEB (2 * TILEB)                // 36864
#define GEMM_SMEM (2 * STAGEB)            // 73728 B

__global__ __launch_bounds__(256, 2) void gemm_tc(
        const __half* __restrict__ A,
        const __half* __restrict__ B0, const __half* __restrict__ B1,
        const __half* __restrict__ B2, int nb0, int nb1,
        float* __restrict__ C, int M, int N, int K) {
    extern __shared__ __align__(16) char smem[];
    const uint32_t sb = smem_u32(smem);

    const int tid = threadIdx.x;
    const int wid = tid >> 5;
    const int lane = tid & 31;
    const int wm = wid & 1;
    const int wn = wid >> 1;
    const int lr = lane >> 2;
    const int lc = lane & 3;

    const size_t row0 = (size_t)blockIdx.y * BM;
    const int col0 = blockIdx.x * BN;

    const __half* B;
    int bo;
    if (col0 < nb0)      { B = B0; bo = col0; }
    else if (col0 < nb1) { B = B1; bo = col0 - nb0; }
    else                 { B = B2; bo = col0 - nb1; }

    // producer mapping: 4 chunks A + 4 chunks B per thread (16B chunks)
    const __half* gA[4];
    const __half* gB[4];
    uint32_t sOff[4];
#pragma unroll
    for (int i = 0; i < 4; i++) {
        int cid = tid + 256 * i;
        int r = cid >> 3, c = cid & 7;
        gA[i] = A + (row0 + r) * (size_t)K + c * 8;
        gB[i] = B + (size_t)(bo + r) * K + c * 8;
        sOff[i] = (uint32_t)(r * ROWB + c * 16);
    }

    // ldmatrix lane-relative offsets
    // A (x4 per mt): rows mt*16 + (lane&15), k-halfgroup (lane>>4)
    uint32_t relA[4];
#pragma unroll
    for (int mt = 0; mt < 4; mt++)
        relA[mt] = (uint32_t)((wm * 64 + mt * 16 + (lane & 15)) * ROWB + (lane >> 4) * 16);
    // B (x4 per nt-pair p): rows (2p + (lane>>4))*8 + (lane&7), k-halfgroup (lane>>3)&1
    uint32_t relB[2];
#pragma unroll
    for (int p = 0; p < 2; p++)
        relB[p] = (uint32_t)((wn * 32 + (2 * p + (lane >> 4)) * 8 + (lane & 7)) * ROWB +
                             ((lane >> 3) & 1) * 16);

    float acc[4][4][4];
#pragma unroll
    for (int mt = 0; mt < 4; mt++)
#pragma unroll
        for (int nt = 0; nt < 4; nt++)
#pragma unroll
            for (int e = 0; e < 4; e++) acc[mt][nt][e] = 0.f;

    const int NKc = K / BK;

#pragma unroll
    for (int st = 0; st < 2; st++) {
        uint32_t base = sb + st * STAGEB;
#pragma unroll
        for (int i = 0; i < 4; i++) {
            cp_async16(base + sOff[i], gA[i] + st * BK);
            cp_async16(base + TILEB + sOff[i], gB[i] + st * BK);
        }
        CP_COMMIT();
    }

    for (int kc = 0; kc < NKc; kc++) {
        CP_WAIT1();
        __syncthreads();

        const uint32_t Abase = sb + (kc & 1) * STAGEB;
        const uint32_t Bbase = Abase + TILEB;

#pragma unroll
        for (int g = 0; g < 4; g++) {
            const uint32_t go = (uint32_t)(g * 32);
            uint32_t af[4][4], bf[4][2];
#pragma unroll
            for (int mt = 0; mt < 4; mt++)
                ldsm_x4(af[mt][0], af[mt][1], af[mt][2], af[mt][3],
                        Abase + relA[mt] + go);
#pragma unroll
            for (int p = 0; p < 2; p++)
                ldsm_x4(bf[2 * p][0], bf[2 * p][1], bf[2 * p + 1][0], bf[2 * p + 1][1],
                        Bbase + relB[p] + go);
#pragma unroll
            for (int mt = 0; mt < 4; mt++)
#pragma unroll
                for (int nt = 0; nt < 4; nt++)
                    mma16816(acc[mt][nt], af[mt][0], af[mt][1], af[mt][2], af[mt][3],
                             bf[nt][0], bf[nt][1]);
        }
        __syncthreads();

        if (kc + 2 < NKc) {
            uint32_t base = sb + (kc & 1) * STAGEB;
            const int koff = (kc + 2) * BK;
#pragma unroll
            for (int i = 0; i < 4; i++) {
                cp_async16(base + sOff[i], gA[i] + koff);
                cp_async16(base + TILEB + sOff[i], gB[i] + koff);
            }
        }
        CP_COMMIT();
    }

#pragma unroll
    for (int mt = 0; mt < 4; mt++) {
        size_t rg = row0 + wm * 64 + mt * 16 + lr;
#pragma unroll
        for (int nt = 0; nt < 4; nt++) {
            size_t cg = (size_t)col0 + wn * 32 + nt * 8 + lc * 2;
            *(float2*)(C + rg * N + cg) = make_float2(acc[mt][nt][0], acc[mt][nt][1]);
            *(float2*)(C + (rg + 8) * N + cg) = make_float2(acc[mt][nt][2], acc[mt][nt][3]);
        }
    }
}

// ==================================================================
// RoPE + fp16 hi/lo split (k16-interleaved, flash-private), warp per row.
// ==================================================================
__global__ void rope_split_kernel(const float* __restrict__ src,
                                  const float* __restrict__ cosp,
                                  const float* __restrict__ sinp,
                                  __half* __restrict__ dst,
                                  int nh, float scale) {
    int wpb = blockDim.x >> 5;
    int idx = blockIdx.x * wpb + (threadIdx.x >> 5);
    int lane = threadIdx.x & 31;
    int s = idx / nh, h = idx - s * nh;
    int d0 = 4 * lane;

    const float* row = src + (size_t)s * QKVN + h * HD;
    float4 x = *(const float4*)(row + d0);
    float4 c = *(const float4*)(cosp + s * HD + d0);
    float4 sn = *(const float4*)(sinp + s * HD + d0);
    float xs[4] = {x.x, x.y, x.z, x.w};
    float cs[4] = {c.x, c.y, c.z, c.w};
    float ss[4] = {sn.x, sn.y, sn.z, sn.w};
    float sign = (lane < 16) ? -1.f : 1.f;
    float out[4];
#pragma unroll
    for (int j = 0; j < 4; j++) {
        float p = __shfl_xor_sync(0xffffffffu, xs[j], 16);
        out[j] = (xs[j] * cs[j] + sign * p * ss[j]) * scale;
    }

    int g = lane >> 2;
    int e = 4 * (lane & 3);
    int s0 = (e < 8) ? e : e - 7;
    int s1 = (e + 2 < 8) ? e + 2 : e - 5;

    __half2 h0 = __floats2half2_rn(out[0], out[1]);
    __half2 h1 = __floats2half2_rn(out[2], out[3]);
    float2 r0 = __half22float2(h0), r1 = __half22float2(h1);
    __half2 l0 = __floats2half2_rn(out[0] - r0.x, out[1] - r0.y);
    __half2 l1 = __floats2half2_rn(out[2] - r1.x, out[3] - r1.y);

    __half2* dh = (__half2*)dst;
    size_t base = (size_t)(s * nh + h) * 128;
    dh[base + g * 8 + s0] = h0;
    dh[base + g * 8 + s1] = h1;
    dh[base + 64 + g * 8 + s0] = l0;
    dh[base + 64 + g * 8 + s1] = l1;
}

// ==================================================================
// V transpose + split (flash-private layout) — unchanged.
// ==================================================================
__global__ __launch_bounds__(256) void convert_v_kernel(const float* __restrict__ qkv,
                                                        __half* __restrict__ vt) {
    __shared__ float vsm[64][132];
    int s0 = blockIdx.x * 64;
    int kvh = blockIdx.y;
    int tid = threadIdx.x;

    for (int i = tid; i < 64 * 32; i += 256) {
        int r = i >> 5, c4 = (i & 31) * 4;
        float4 v = *(const float4*)(qkv + (size_t)(s0 + r) * QKVN + 5120 + kvh * HD + c4);
        vsm[r][c4] = v.x; vsm[r][c4 + 1] = v.y; vsm[r][c4 + 2] = v.z; vsm[r][c4 + 3] = v.w;
    }
    __syncthreads();

    int d = tid >> 1, hp = tid & 1;
    float v[32];
#pragma unroll
    for (int j = 0; j < 32; j++) v[j] = vsm[32 * hp + j][d];

#pragma unroll
    for (int g2 = 0; g2 < 2; g2++) {
        __half2 hi[8], lo[8];
#pragma unroll
        for (int slot = 0; slot < 8; slot++) {
            int e = (slot & 1) ? slot + 7 : slot;
            float x = v[g2 * 16 + e], y = v[g2 * 16 + e + 1];
            __half2 hh = __floats2half2_rn(x, y);
            float2 r = __half22float2(hh);
            hi[slot] = hh;
            lo[slot] = __floats2half2_rn(x - r.x, y - r.y);
        }
        int kbase = s0 + (2 * hp + g2) * 16;
        __half2* dhi = (__half2*)vt + ((((size_t)kvh * 2 + 0) * HD + d) * S + kbase) / 2;
        __half2* dlo = (__half2*)vt + ((((size_t)kvh * 2 + 1) * HD + d) * S + kbase) / 2;
#pragma unroll
        for (int slot = 0; slot < 8; slot++) { dhi[slot] = hi[slot]; dlo[slot] = lo[slot]; }
    }
}

// ==================================================================
// Flash attention (unchanged internals), epilogue now writes PLAIN
// fp16 att rows (out-proj A operand layout).
// ==================================================================
#define FQ 64
#define FK 64
#define QROWB 288
#define VROWB 160
#define Q_PLANE (64 * QROWB)
#define KV_OFF (2 * Q_PLANE)
#define KV_BYTES 40960
#define P_OFF (KV_OFF + KV_BYTES)
#define PS 72
#define FLASH_SMEM (P_OFF + 64 * PS * 4)   // 96256 B

__global__ __launch_bounds__(128) void flash_tc(const __half* __restrict__ Qsg,
                                                const __half* __restrict__ Ksg,
                                                const __half* __restrict__ VTg,
                                                __half* __restrict__ Oh) {
    extern __shared__ __align__(16) char fsm[];
    const uint32_t qhi_b = smem_u32(fsm);
    const uint32_t qlo_b = qhi_b + Q_PLANE;
    const uint32_t kv_b  = qhi_b + KV_OFF;
    const uint32_t klo_b = kv_b + 64 * QROWB;
    const uint32_t vlo_b = kv_b + 128 * VROWB;
    float* Ps = (float*)(fsm + P_OFF);

    const int h = blockIdx.y;
    const int kvh = h >> 2;
    const int qi = gridDim.x - 1 - blockIdx.x;
    const int q0 = qi * FQ;
    const int tid = threadIdx.x;
    const int wid = tid >> 5;
    const int lane = tid & 31;
    const int lr = lane >> 2;
    const int lc = lane & 3;

#pragma unroll
    for (int ii = 0; ii < 16; ii++) {
        int i = tid + 128 * ii;
        int r = i >> 5, c = i & 31;
        int plane = c >> 4, j = c & 15;
        cp_async16((plane ? qlo_b : qhi_b) + (uint32_t)(r * QROWB + j * 16),
                   Qsg + ((size_t)(q0 + r) * NH + h) * 256 + plane * 128 + j * 8);
    }
    CP_COMMIT();

    float o[16][4];
#pragma unroll
    for (int nt = 0; nt < 16; nt++)
#pragma unroll
        for (int e = 0; e < 4; e++) o[nt][e] = 0.f;
    float m0 = -1e30f, m1 = -1e30f, l0v = 0.f, l1v = 0.f;

    float* Pw = Ps + wid * 16 * PS;

    const int nkt = qi + 1;
    for (int kt = 0; kt < nkt; kt++) {
        const int k0 = kt * FK;

#pragma unroll
        for (int ii = 0; ii < 16; ii++) {
            int i = tid + 128 * ii;
            int r = i >> 5, c = i & 31;
            int plane = c >> 4, j = c & 15;
            cp_async16((plane ? klo_b : kv_b) + (uint32_t)(r * QROWB + j * 16),
                       Ksg + ((size_t)(k0 + r) * NKV + kvh) * 256 + plane * 128 + j * 8);
        }
        CP_COMMIT();
        CP_WAIT0();
        __syncthreads();

        float sa[8][4];
#pragma unroll
        for (int nt = 0; nt < 8; nt++)
#pragma unroll
            for (int e = 0; e < 4; e++) sa[nt][e] = 0.f;

#pragma unroll 2
        for (int ks = 0; ks < 8; ks++) {
            const uint32_t go = (uint32_t)(ks * 32 + lc * 8);
            uint32_t ah[4], al[4];
            {
                uint32_t r = (uint32_t)((wid * 16 + lr) * QROWB) + go;
                lds64(ah[0], ah[2], qhi_b + r);
                lds64(ah[1], ah[3], qhi_b + r + 8 * QROWB);
                lds64(al[0], al[2], qlo_b + r);
                lds64(al[1], al[3], qlo_b + r + 8 * QROWB);
            }
#pragma unroll
            for (int nt = 0; nt < 8; nt++) {
                uint32_t r = (uint32_t)((nt * 8 + lr) * QROWB) + go;
                uint32_t bh0, bh1, bl0, bl1;
                lds64(bh0, bh1, kv_b + r);
                lds64(bl0, bl1, klo_b + r);
                mma16816(sa[nt], ah[0], ah[1], ah[2], ah[3], bh0, bh1);
                mma16816(sa[nt], ah[0], ah[1], ah[2], ah[3], bl0, bl1);
                mma16816(sa[nt], al[0], al[1], al[2], al[3], bh0, bh1);
            }
        }
        __syncthreads();

#pragma unroll
        for (int ii = 0; ii < 16; ii++) {
            int i = tid + 128 * ii;
            int plane = i >> 10;
            int rem = i & 1023;
            int d = rem >> 3, j = rem & 7;
            cp_async16((plane ? vlo_b : kv_b) + (uint32_t)(d * VROWB + j * 16),
                       VTg + (((size_t)kvh * 2 + plane) * HD + d) * S + k0 + j * 8);
        }
        CP_COMMIT();

        if (kt == qi) {
            int r0 = q0 + wid * 16 + lr;
#pragma unroll
            for (int nt = 0; nt < 8; nt++) {
                int c = k0 + nt * 8 + lc * 2;
                if (c > r0)         sa[nt][0] = -1e30f;
                if (c + 1 > r0)     sa[nt][1] = -1e30f;
                if (c > r0 + 8)     sa[nt][2] = -1e30f;
                if (c + 1 > r0 + 8) sa[nt][3] = -1e30f;
            }
        }

        float rx0 = -1e30f, rx1 = -1e30f;
#pragma unroll
        for (int nt = 0; nt < 8; nt++) {
            rx0 = fmaxf(rx0, fmaxf(sa[nt][0], sa[nt][1]));
            rx1 = fmaxf(rx1, fmaxf(sa[nt][2], sa[nt][3]));
        }
        rx0 = fmaxf(rx0, __shfl_xor_sync(0xffffffffu, rx0, 1));
        rx0 = fmaxf(rx0, __shfl_xor_sync(0xffffffffu, rx0, 2));
        rx1 = fmaxf(rx1, __shfl_xor_sync(0xffffffffu, rx1, 1));
        rx1 = fmaxf(rx1, __shfl_xor_sync(0xffffffffu, rx1, 2));

        float mn0 = fmaxf(m0, rx0), mn1 = fmaxf(m1, rx1);
        float a0 = __expf(m0 - mn0), a1 = __expf(m1 - mn1);
        m0 = mn0; m1 = mn1;

        float rs0 = 0.f, rs1 = 0.f;
#pragma unroll
        for (int nt = 0; nt < 8; nt++) {
            sa[nt][0] = __expf(sa[nt][0] - mn0);
            sa[nt][1] = __expf(sa[nt][1] - mn0);
            sa[nt][2] = __expf(sa[nt][2] - mn1);
            sa[nt][3] = __expf(sa[nt][3] - mn1);
            rs0 += sa[nt][0] + sa[nt][1];
            rs1 += sa[nt][2] + sa[nt][3];
        }
        rs0 += __shfl_xor_sync(0xffffffffu, rs0, 1);
        rs0 += __shfl_xor_sync(0xffffffffu, rs0, 2);
        rs1 += __shfl_xor_sync(0xffffffffu, rs1, 1);
        rs1 += __shfl_xor_sync(0xffffffffu, rs1, 2);
        l0v = l0v * a0 + rs0;
        l1v = l1v * a1 + rs1;

#pragma unroll
        for (int nt = 0; nt < 16; nt++) {
            o[nt][0] *= a0; o[nt][1] *= a0;
            o[nt][2] *= a1; o[nt][3] *= a1;
        }

#pragma unroll
        for (int nt = 0; nt < 8; nt++) {
            *(float2*)(Pw + lr * PS + nt * 8 + 2 * lc) = make_float2(sa[nt][0], sa[nt][1]);
            *(float2*)(Pw + (lr + 8) * PS + nt * 8 + 2 * lc) = make_float2(sa[nt][2], sa[nt][3]);
        }
        __syncwarp();

        CP_WAIT0();
        __syncthreads();

#pragma unroll
        for (int ks = 0; ks < 4; ks++) {
            const int kk = ks * 16;
            uint32_t ah[4], al[4];
            {
                const float* p = Pw + lr * PS + kk + 2 * lc;
                split2(p[0], p[1], ah[0], al[0]);
                split2(p[8 * PS], p[8 * PS + 1], ah[1], al[1]);
                split2(p[8], p[9], ah[2], al[2]);
                split2(p[8 * PS + 8], p[8 * PS + 9], ah[3], al[3]);
            }
            const uint32_t go = (uint32_t)(ks * 32 + lc * 8);
#pragma unroll
            for (int nt = 0; nt < 16; nt++) {
                uint32_t r = (uint32_t)((nt * 8 + lr) * VROWB) + go;
                uint32_t bh0, bh1, bl0, bl1;
                lds64(bh0, bh1, kv_b + r);
                lds64(bl0, bl1, vlo_b + r);
                mma16816(o[nt], ah[0], ah[1], ah[2], ah[3], bh0, bh1);
                mma16816(o[nt], ah[0], ah[1], ah[2], ah[3], bl0, bl1);
                mma16816(o[nt], al[0], al[1], al[2], al[3], bh0, bh1);
            }
        }
        __syncthreads();
    }

    // epilogue: PLAIN fp16 att rows
    float inv0 = 1.0f / l0v, inv1 = 1.0f / l1v;
    size_t r0 = q0 + wid * 16 + lr;
#pragma unroll
    for (int nt = 0; nt < 16; nt++) {
        size_t c = h * HD + nt * 8 + lc * 2;
        __half2 v0 = __floats2half2_rn(o[nt][0] * inv0, o[nt][1] * inv0);
        __half2 v1 = __floats2half2_rn(o[nt][2] * inv1, o[nt][3] * inv1);
        *(__half2*)(Oh + r0 * (NH * HD) + c) = v0;
        *(__half2*)(Oh + (r0 + 8) * (NH * HD) + c) = v1;
    }
}

// ---------------- launch ----------------
extern "C" void kernel_launch(void* const* d_in, const int* in_sizes, int n_in,
                              void* d_out, int out_size) {
    const float* hs   = (const float*)d_in[0];
    const float* cosp = (const float*)d_in[2];
    const float* sinp = (const float*)d_in[3];
    const float* wq   = (const float*)d_in[4];
    const float* wk   = (const float*)d_in[5];
    const float* wv   = (const float*)d_in[6];
    const float* wo   = (const float*)d_in[7];
    float* out = (float*)d_out;

    float* qkv;
    __half *ath, *hsh, *wqh, *wkh, *wvh, *woh, *qs, *ks, *vt;
    cudaGetSymbolAddress((void**)&qkv, g_qkv);
    cudaGetSymbolAddress((void**)&ath, g_att_h);
    cudaGetSymbolAddress((void**)&hsh, g_hs_h);
    cudaGetSymbolAddress((void**)&wqh, g_wq_h);
    cudaGetSymbolAddress((void**)&wkh, g_wk_h);
    cudaGetSymbolAddress((void**)&wvh, g_wv_h);
    cudaGetSymbolAddress((void**)&woh, g_wo_h);
    cudaGetSymbolAddress((void**)&qs, g_q_s);
    cudaGetSymbolAddress((void**)&ks, g_k_s);
    cudaGetSymbolAddress((void**)&vt, g_vt);

    cudaFuncSetAttribute(gemm_tc,
                         cudaFuncAttributeMaxDynamicSharedMemorySize, GEMM_SMEM);
    cudaFuncSetAttribute(flash_tc,
                         cudaFuncAttributeMaxDynamicSharedMemorySize, FLASH_SMEM);

    const int RT = 256;
    const int n8_hs = S * HID / 8;
    const int n8_wq = NH * HD * HID / 8;
    const int n8_wk = NKV * HD * HID / 8;
    const float scale = 0.08838834764831845f;

    round_fp16_kernel<<<(n8_hs + RT - 1) / RT, RT>>>(hs, hsh, n8_hs);
    round_fp16_kernel<<<(n8_wq + RT - 1) / RT, RT>>>(wq, wqh, n8_wq);
    round2_fp16_kernel<<<(2 * n8_wk + RT - 1) / RT, RT>>>(wk, wkh, n8_wk, wv, wvh, n8_wk);
    // fused QKV projection — ncu capture slot
    gemm_tc<<<dim3(QKVN / BN, S / BM), 256, GEMM_SMEM>>>(
        hsh, wqh, wkh, wvh, NH * HD, NH * HD + NKV * HD, qkv, S, QKVN, HID);
    round_fp16_kernel<<<(n8_wq + RT - 1) / RT, RT>>>(wo, woh, n8_wq);
    rope_split_kernel<<<S * NH / 8, 256>>>(qkv, cosp, sinp, qs, NH, scale);
    rope_split_kernel<<<S * NKV / 8, 256>>>(qkv + 4096, cosp, sinp, ks, NKV, 1.0f);
    convert_v_kernel<<<dim3(S / 64, NKV), 256>>>(qkv, vt);
    flash_tc<<<dim3(S / FQ, NH), 128, FLASH_SMEM>>>(qs, ks, vt, ath);
    gemm_tc<<<dim3(HID / BN, S / BM), 256, GEMM_SMEM>>>(
        ath, woh, woh, woh, HID, HID, out, S, HID, HID);
}